// round 10
// baseline (speedup 1.0000x reference)
#include <cuda_runtime.h>
#include <cuda_bf16.h>
#include <math.h>
#include <stdint.h>

#define Bb   16
#define Mt   16
#define Dd   512
#define Ne   16
#define Hh   682
#define NHt  (Ne*Hh)      /* 10912 */
#define Rows (Bb*Mt)      /* 256   */
#define OUTD 512
#define YSPLIT 16
#define OSPLIT 64

typedef unsigned long long ull;
typedef __nv_bfloat16 bf16;

// ---- warp mma: D(16x8 f32) += A(16x16 bf16) * B(16x8 bf16) ----
__device__ __forceinline__ void mma_bf16(float* c, uint32_t a0, uint32_t a1, uint32_t a2, uint32_t a3,
                                         uint32_t b0, uint32_t b1) {
    asm volatile("mma.sync.aligned.m16n8k16.row.col.f32.bf16.bf16.f32 "
        "{%0,%1,%2,%3}, {%4,%5,%6,%7}, {%8,%9}, {%0,%1,%2,%3};"
        : "+f"(c[0]), "+f"(c[1]), "+f"(c[2]), "+f"(c[3])
        : "r"(a0), "r"(a1), "r"(a2), "r"(a3), "r"(b0), "r"(b1));
}

__device__ __forceinline__ void split2(float v, bf16& h, bf16& l) {
    h = __float2bfloat16(v);
    l = __float2bfloat16(v - __bfloat162float(h));
}
__device__ __forceinline__ void st_split(bf16* gh, bf16* gl, long long idx, float v) {
    bf16 h, l; split2(v, h, l);
    gh[idx] = h; gl[idx] = l;
}
__device__ __forceinline__ void pksp(float x, float y, uint32_t& hr, uint32_t& lr) {
    bf16 hx, lx, hy, ly;
    split2(x, hx, lx); split2(y, hy, ly);
    __nv_bfloat162 H; H.x = hx; H.y = hy;
    __nv_bfloat162 L; L.x = lx; L.y = ly;
    hr = *(uint32_t*)&H; lr = *(uint32_t*)&L;
}

// ---------------- scratch ----------------
__device__ float g_logits[Rows*NHt];
__device__ float g_XW1[Rows*NHt];
__device__ float g_Ypart[YSPLIT*Rows*OUTD];
__device__ float g_b2sum[OUTD];
__device__ float g_opart[OSPLIT*Bb*OUTD];
__device__ bf16 g_xh[Rows*Dd],  g_xl[Rows*Dd];
__device__ bf16 g_gh[Rows*NHt], g_gl[Rows*NHt];
__device__ bf16 g_chh[Rows*NHt], g_chl[Rows*NHt];

// ---------------- prep: x split + b2sum in one kernel ----------------
#define CVT_BLOCKS (Rows*Dd/4/256)      /* 128 */
__global__ void prep_k(const float* __restrict__ src, bf16* __restrict__ hi,
                       bf16* __restrict__ lo, const float* __restrict__ b2,
                       float* __restrict__ b2s)
{
    const int bx = blockIdx.x;
    if (bx < CVT_BLOCKS) {
        const int i = bx * 256 + threadIdx.x;
        const float4 v = ((const float4*)src)[i];
        bf16 h[4], l[4];
        const float vv[4] = {v.x, v.y, v.z, v.w};
        #pragma unroll
        for (int e = 0; e < 4; ++e) split2(vv[e], h[e], l[e]);
        *(ull*)(hi + i * 4) = *(const ull*)h;
        *(ull*)(lo + i * 4) = *(const ull*)l;
    } else {
        const int d = (bx - CVT_BLOCKS) * 256 + threadIdx.x;
        if (d < OUTD) {
            float s = 0.f;
            #pragma unroll
            for (int n = 0; n < Ne; ++n) s += b2[n * OUTD + d];
            b2s[d] = s;
        }
    }
}

// ---------------- shared smem layout for tensor GEMMs ----------------
#define AS_STR 72
#define BS_STR 74
#define SM_AH 0
#define SM_AL (SM_AH + 128*AS_STR*2)
#define SM_BH (SM_AL + 128*AS_STR*2)
#define SM_BL (SM_BH + 64*BS_STR*2)
#define MG_SMEM (SM_BL + 64*BS_STR*2)    /* 55808 */

// ---------------- dual GEMM: one launch computes logits (phi) AND XW1 (W1) ----------------
// blockIdx.z = 0: B = phi row-major [Dd, NHt] -> C0 = logits
// blockIdx.z = 1: B[k][j] = W1[n][k][h], j=n*Hh+h -> C1 = XW1
// Mtile=128 x Ntile=64; 8 warps 4m x 2n; K = Dd (8 chunks of 64).
__global__ __launch_bounds__(256) void dual_gemm(
    const bf16* __restrict__ Ah, const bf16* __restrict__ Al,
    const float* __restrict__ B0, const float* __restrict__ B1,
    float* __restrict__ C0, float* __restrict__ C1)
{
    extern __shared__ __align__(16) char sm[];
    bf16* sAh = (bf16*)(sm + SM_AH);
    bf16* sAl = (bf16*)(sm + SM_AL);
    bf16* sBh = (bf16*)(sm + SM_BH);
    bf16* sBl = (bf16*)(sm + SM_BL);

    const int t = threadIdx.x;
    const int lane = t & 31, warp = t >> 5;
    const int wm = (warp & 3) * 32;
    const int wn = (warp >> 2) * 32;
    const int m0 = blockIdx.y * 128;
    const int j0 = blockIdx.x * 64;
    const int mode = blockIdx.z;
    const float* __restrict__ Bm = mode ? B1 : B0;
    float* __restrict__ C = mode ? C1 : C0;

    float acc[2][4][4];
    #pragma unroll
    for (int i = 0; i < 2; ++i)
        #pragma unroll
        for (int j = 0; j < 4; ++j)
            #pragma unroll
            for (int e = 0; e < 4; ++e) acc[i][j][e] = 0.f;

    const int gid = lane >> 2;
    const int qid = lane & 3;

    int bn[4], bh[4];
    if (mode) {
        #pragma unroll
        for (int it = 0; it < 4; ++it) {
            const int g = (t + it * 256) & 15;
            const int j = j0 + g * 4;
            int n = j / Hh;
            bn[it] = n;
            bh[it] = j - n * Hh;
        }
    }

    for (int c = 0; c < Dd / 64; ++c) {
        const int k0 = c << 6;
        __syncthreads();
        #pragma unroll
        for (int it = 0; it < 8; ++it) {
            const int s = t + it * 256;
            const int kq = s & 15;
            const int row = s >> 4;
            const long long ga = (long long)(m0 + row) * Dd + k0 + kq * 4;
            ull vh = *(const ull*)(Ah + ga);
            ull vl = *(const ull*)(Al + ga);
            *(ull*)(sAh + row * AS_STR + kq * 4) = vh;
            *(ull*)(sAl + row * AS_STR + kq * 4) = vl;
        }
        #pragma unroll
        for (int it = 0; it < 4; ++it) {
            const int s = t + it * 256;
            const int g = s & 15;
            const int k = s >> 4;
            const int gj = j0 + g * 4;
            const int gk = k0 + k;
            float vv[4] = {0.f, 0.f, 0.f, 0.f};
            if (mode == 0) {
                if (gj + 4 <= NHt) {
                    const float4 v = *(const float4*)(Bm + (long long)gk * NHt + gj);
                    vv[0] = v.x; vv[1] = v.y; vv[2] = v.z; vv[3] = v.w;
                }
            } else {
                int n = bn[it], h = bh[it];
                #pragma unroll
                for (int e = 0; e < 4; ++e) {
                    if (gj + e < NHt) vv[e] = Bm[((long long)n * Dd + gk) * Hh + h];
                    if (++h >= Hh) { h = 0; ++n; }
                }
            }
            #pragma unroll
            for (int e = 0; e < 4; ++e) {
                bf16 h, l; split2(vv[e], h, l);
                sBh[(g * 4 + e) * BS_STR + k] = h;
                sBl[(g * 4 + e) * BS_STR + k] = l;
            }
        }
        __syncthreads();

        #pragma unroll
        for (int ks = 0; ks < 4; ++ks) {
            const int kcol = ks * 16 + qid * 2;
            uint32_t ah[2][4], al[2][4];
            #pragma unroll
            for (int mi = 0; mi < 2; ++mi) {
                const int r = wm + mi * 16 + gid;
                ah[mi][0] = *(const uint32_t*)(sAh + r * AS_STR + kcol);
                ah[mi][1] = *(const uint32_t*)(sAh + (r + 8) * AS_STR + kcol);
                ah[mi][2] = *(const uint32_t*)(sAh + r * AS_STR + kcol + 8);
                ah[mi][3] = *(const uint32_t*)(sAh + (r + 8) * AS_STR + kcol + 8);
                al[mi][0] = *(const uint32_t*)(sAl + r * AS_STR + kcol);
                al[mi][1] = *(const uint32_t*)(sAl + (r + 8) * AS_STR + kcol);
                al[mi][2] = *(const uint32_t*)(sAl + r * AS_STR + kcol + 8);
                al[mi][3] = *(const uint32_t*)(sAl + (r + 8) * AS_STR + kcol + 8);
            }
            uint32_t bhf[4][2], blf[4][2];
            #pragma unroll
            for (int ni = 0; ni < 4; ++ni) {
                const int n = wn + ni * 8 + gid;
                bhf[ni][0] = *(const uint32_t*)(sBh + n * BS_STR + kcol);
                bhf[ni][1] = *(const uint32_t*)(sBh + n * BS_STR + kcol + 8);
                blf[ni][0] = *(const uint32_t*)(sBl + n * BS_STR + kcol);
                blf[ni][1] = *(const uint32_t*)(sBl + n * BS_STR + kcol + 8);
            }
            #pragma unroll
            for (int mi = 0; mi < 2; ++mi)
                #pragma unroll
                for (int ni = 0; ni < 4; ++ni) {
                    mma_bf16(acc[mi][ni], ah[mi][0], ah[mi][1], ah[mi][2], ah[mi][3],
                             bhf[ni][0], bhf[ni][1]);
                    mma_bf16(acc[mi][ni], ah[mi][0], ah[mi][1], ah[mi][2], ah[mi][3],
                             blf[ni][0], blf[ni][1]);
                    mma_bf16(acc[mi][ni], al[mi][0], al[mi][1], al[mi][2], al[mi][3],
                             bhf[ni][0], bhf[ni][1]);
                }
        }
    }

    #pragma unroll
    for (int mi = 0; mi < 2; ++mi) {
        const int r0 = m0 + wm + mi * 16 + gid;
        #pragma unroll
        for (int ni = 0; ni < 4; ++ni) {
            const int cn = j0 + wn + ni * 8 + qid * 2;
            if (cn < NHt) {
                float2 lo2 = make_float2(acc[mi][ni][0], acc[mi][ni][1]);
                float2 hi2 = make_float2(acc[mi][ni][2], acc[mi][ni][3]);
                *(float2*)(C + (long long)r0 * NHt + cn)       = lo2;
                *(float2*)(C + (long long)(r0 + 8) * NHt + cn) = hi2;
            }
        }
    }
}

// ---------------- Y GEMM (split-K): C partials = A[256,NHt] @ W2[NHt,OUTD] ----------------
__global__ __launch_bounds__(256) void y_gemm(
    const bf16* __restrict__ Ah, const bf16* __restrict__ Al,
    const float* __restrict__ Bm,
    float* __restrict__ C)
{
    extern __shared__ __align__(16) char sm[];
    bf16* sAh = (bf16*)(sm + SM_AH);
    bf16* sAl = (bf16*)(sm + SM_AL);
    bf16* sBh = (bf16*)(sm + SM_BH);
    bf16* sBl = (bf16*)(sm + SM_BL);

    const int t = threadIdx.x;
    const int lane = t & 31, warp = t >> 5;
    const int wm = (warp & 3) * 32;
    const int wn = (warp >> 2) * 32;
    const int m0 = blockIdx.y * 128;
    const int j0 = blockIdx.x * 64;
    const int z  = blockIdx.z;
    const int nch = (NHt + 63) >> 6;  // 171
    const int c0 = (int)((long long)nch * z / YSPLIT);
    const int c1 = (int)((long long)nch * (z + 1) / YSPLIT);

    float acc[2][4][4];
    #pragma unroll
    for (int i = 0; i < 2; ++i)
        #pragma unroll
        for (int j = 0; j < 4; ++j)
            #pragma unroll
            for (int e = 0; e < 4; ++e) acc[i][j][e] = 0.f;

    const int gid = lane >> 2;
    const int qid = lane & 3;

    for (int c = c0; c < c1; ++c) {
        const int k0 = c << 6;
        __syncthreads();
        #pragma unroll
        for (int it = 0; it < 8; ++it) {
            const int s = t + it * 256;
            const int kq = s & 15;
            const int row = s >> 4;
            const int gk = k0 + kq * 4;
            const long long ga = (long long)(m0 + row) * NHt + gk;
            ull vh = 0, vl = 0;
            if (gk + 4 <= NHt) { vh = *(const ull*)(Ah + ga); vl = *(const ull*)(Al + ga); }
            *(ull*)(sAh + row * AS_STR + kq * 4) = vh;
            *(ull*)(sAl + row * AS_STR + kq * 4) = vl;
        }
        #pragma unroll
        for (int it = 0; it < 4; ++it) {
            const int s = t + it * 256;
            const int g = s & 15;
            const int k = s >> 4;
            const int gj = j0 + g * 4;
            const int gk = k0 + k;
            float vv[4] = {0.f, 0.f, 0.f, 0.f};
            if (gk < NHt) {
                const float4 v = *(const float4*)(Bm + (long long)gk * OUTD + gj);
                vv[0] = v.x; vv[1] = v.y; vv[2] = v.z; vv[3] = v.w;
            }
            #pragma unroll
            for (int e = 0; e < 4; ++e) {
                bf16 h, l; split2(vv[e], h, l);
                sBh[(g * 4 + e) * BS_STR + k] = h;
                sBl[(g * 4 + e) * BS_STR + k] = l;
            }
        }
        __syncthreads();

        #pragma unroll
        for (int ks = 0; ks < 4; ++ks) {
            const int kcol = ks * 16 + qid * 2;
            uint32_t ah[2][4], al[2][4];
            #pragma unroll
            for (int mi = 0; mi < 2; ++mi) {
                const int r = wm + mi * 16 + gid;
                ah[mi][0] = *(const uint32_t*)(sAh + r * AS_STR + kcol);
                ah[mi][1] = *(const uint32_t*)(sAh + (r + 8) * AS_STR + kcol);
                ah[mi][2] = *(const uint32_t*)(sAh + r * AS_STR + kcol + 8);
                ah[mi][3] = *(const uint32_t*)(sAh + (r + 8) * AS_STR + kcol + 8);
                al[mi][0] = *(const uint32_t*)(sAl + r * AS_STR + kcol);
                al[mi][1] = *(const uint32_t*)(sAl + (r + 8) * AS_STR + kcol);
                al[mi][2] = *(const uint32_t*)(sAl + r * AS_STR + kcol + 8);
                al[mi][3] = *(const uint32_t*)(sAl + (r + 8) * AS_STR + kcol + 8);
            }
            uint32_t bhf[4][2], blf[4][2];
            #pragma unroll
            for (int ni = 0; ni < 4; ++ni) {
                const int n = wn + ni * 8 + gid;
                bhf[ni][0] = *(const uint32_t*)(sBh + n * BS_STR + kcol);
                bhf[ni][1] = *(const uint32_t*)(sBh + n * BS_STR + kcol + 8);
                blf[ni][0] = *(const uint32_t*)(sBl + n * BS_STR + kcol);
                blf[ni][1] = *(const uint32_t*)(sBl + n * BS_STR + kcol + 8);
            }
            #pragma unroll
            for (int mi = 0; mi < 2; ++mi)
                #pragma unroll
                for (int ni = 0; ni < 4; ++ni) {
                    mma_bf16(acc[mi][ni], ah[mi][0], ah[mi][1], ah[mi][2], ah[mi][3],
                             bhf[ni][0], bhf[ni][1]);
                    mma_bf16(acc[mi][ni], ah[mi][0], ah[mi][1], ah[mi][2], ah[mi][3],
                             blf[ni][0], blf[ni][1]);
                    mma_bf16(acc[mi][ni], al[mi][0], al[mi][1], al[mi][2], al[mi][3],
                             bhf[ni][0], bhf[ni][1]);
                }
        }
    }

    float* Cz = C + (long long)z * Rows * OUTD;
    #pragma unroll
    for (int mi = 0; mi < 2; ++mi) {
        const int r0 = m0 + wm + mi * 16 + gid;
        #pragma unroll
        for (int ni = 0; ni < 4; ++ni) {
            const int cn = j0 + wn + ni * 8 + qid * 2;
            float2 lo2 = make_float2(acc[mi][ni][0], acc[mi][ni][1]);
            float2 hi2 = make_float2(acc[mi][ni][2], acc[mi][ni][3]);
            *(float2*)(Cz + (long long)r0 * OUTD + cn)       = lo2;
            *(float2*)(Cz + (long long)(r0 + 8) * OUTD + cn) = hi2;
        }
    }
}

// ---------------- softmax_np: Cw = softmax_p(softmax_n(L)) -> bf16 hi/lo ----------------
__global__ void softmax_np(const float* __restrict__ L, bf16* __restrict__ chh,
                           bf16* __restrict__ chl)
{
    __shared__ float s[Ne * 688];
    const int bm  = blockIdx.x;
    const int tid = threadIdx.x;
    const float* Lrow = L + bm * NHt;

    for (int i4 = tid; i4 < NHt / 4; i4 += 256) {
        const float4 v = *(const float4*)(Lrow + i4 * 4);
        const int idx = i4 * 4;
        const int n = idx / Hh;
        const int p = idx - n * Hh;
        float vv[4] = {v.x, v.y, v.z, v.w};
        int nn = n, pp = p;
        #pragma unroll
        for (int e = 0; e < 4; ++e) {
            s[nn * 688 + pp] = vv[e];
            if (++pp >= Hh) { pp = 0; ++nn; }
        }
    }
    __syncthreads();

    for (int p = tid; p < Hh; p += 256) {
        float mx = -3.4e38f;
        #pragma unroll
        for (int n = 0; n < Ne; ++n) mx = fmaxf(mx, s[n * 688 + p]);
        float sum = 0.f;
        #pragma unroll
        for (int n = 0; n < Ne; ++n) {
            const float e = expf(s[n * 688 + p] - mx);
            s[n * 688 + p] = e;
            sum += e;
        }
        const float inv = 1.f / sum;
        #pragma unroll
        for (int n = 0; n < Ne; ++n) s[n * 688 + p] *= inv;
    }
    __syncthreads();

    const int warp = tid >> 5, lane = tid & 31;
    for (int n = warp; n < Ne; n += 8) {
        float mx = -3.4e38f;
        for (int p = lane; p < Hh; p += 32) mx = fmaxf(mx, s[n * 688 + p]);
        #pragma unroll
        for (int o = 16; o; o >>= 1) mx = fmaxf(mx, __shfl_xor_sync(0xffffffffu, mx, o));
        float sum = 0.f;
        for (int p = lane; p < Hh; p += 32) {
            const float e = expf(s[n * 688 + p] - mx);
            s[n * 688 + p] = e;
            sum += e;
        }
        #pragma unroll
        for (int o = 16; o; o >>= 1) sum += __shfl_xor_sync(0xffffffffu, sum, o);
        const float inv = 1.f / sum;
        for (int p = lane; p < Hh; p += 32) {
            bf16 h, l; split2(s[n * 688 + p] * inv, h, l);
            const long long o2 = (long long)bm * NHt + n * Hh + p;
            chh[o2] = h; chl[o2] = l;
        }
    }
}

// ---------------- TENSOR fused: inline Dw-softmax + mix -> relu -> combine ----------------
#define XH_STR 18
#define FG_SXH 0
#define FG_SXL (FG_SXH + 688*XH_STR*2)
#define FG_SHH (FG_SXL + 688*XH_STR*2)
#define FG_SHL (FG_SHH + 688*XH_STR*2)
#define FG_SB   (FG_SHL + 688*XH_STR*2)
#define FG_SMX  (FG_SB  + 688*4)
#define FG_SINV (FG_SMX + 688*4)
#define FG_SMEM (FG_SINV + 688*4)       /* 107328 */

__global__ __launch_bounds__(256) void fused_G_tc(const float* __restrict__ XW1,
                                                  const float* __restrict__ Lg,
                                                  const bf16* __restrict__ chh,
                                                  const bf16* __restrict__ chl,
                                                  const float* __restrict__ b1,
                                                  bf16* __restrict__ gh,
                                                  bf16* __restrict__ gl)
{
    extern __shared__ __align__(16) char sm[];
    bf16*  sXh = (bf16*)(sm + FG_SXH);
    bf16*  sXl = (bf16*)(sm + FG_SXL);
    bf16*  sHh = (bf16*)(sm + FG_SHH);
    bf16*  sHl = (bf16*)(sm + FG_SHL);
    float* sb   = (float*)(sm + FG_SB);
    float* smx  = (float*)(sm + FG_SMX);
    float* sinv = (float*)(sm + FG_SINV);

    const int bx = blockIdx.x;
    const int n  = bx & (Ne - 1);
    const int b  = bx >> 4;
    const int t = threadIdx.x;
    const int w = t >> 5, lane = t & 31;
    const int gid = lane >> 2, qid = lane & 3;
    const long long mstep = (long long)NHt;

    for (int p = t; p < 688; p += 256) {
        if (p < Hh) {
            const long long base = ((long long)(b * Mt) * Ne + n) * Hh + p;
            float v[Mt], mx = -3.4e38f;
            #pragma unroll
            for (int m = 0; m < Mt; ++m) { v[m] = Lg[base + m * mstep]; mx = fmaxf(mx, v[m]); }
            float sum = 0.f;
            #pragma unroll
            for (int m = 0; m < Mt; ++m) sum += expf(v[m] - mx);
            smx[p] = mx; sinv[p] = 1.f / sum;
        } else { smx[p] = 0.f; sinv[p] = 0.f; }
        sb[p] = (p < Hh) ? b1[n * Hh + p] : 0.f;
    }

    #pragma unroll 1
    for (int mm = 0; mm < Mt; ++mm) {
        const long long rb = ((long long)(b * Mt + mm) * Ne + n) * Hh;
        for (int h = t; h < 688; h += 256) {
            const float v = (h < Hh) ? XW1[rb + h] : 0.f;
            bf16 hi, lo; split2(v, hi, lo);
            sXh[h * XH_STR + mm] = hi;
            sXl[h * XH_STR + mm] = lo;
        }
    }
    __syncthreads();

    float acc[11][4];
    #pragma unroll
    for (int i = 0; i < 11; ++i)
        #pragma unroll
        for (int e = 0; e < 4; ++e) acc[i][e] = 0.f;

    const int NCH = (Hh + 15) / 16;

    for (int c = 0; c < NCH; ++c) {
        const int P0 = c * 16;
        const int pA = P0 + gid, pB = pA + 8;
        const bool vA = (pA < Hh), vB = (pB < Hh);
        const int m0 = qid * 2;
        const long long d0 = ((long long)(b * Mt + m0) * Ne + n) * Hh;
        const float mxA = smx[pA], ivA = sinv[pA];
        const float mxB = smx[pB], ivB = sinv[pB];
        uint32_t dah[4], dal[4];
        {
            float e00 = vA ? expf(Lg[d0 + pA]             - mxA) * ivA : 0.f;
            float e01 = vA ? expf(Lg[d0 + mstep + pA]     - mxA) * ivA : 0.f;
            float e10 = vB ? expf(Lg[d0 + pB]             - mxB) * ivB : 0.f;
            float e11 = vB ? expf(Lg[d0 + mstep + pB]     - mxB) * ivB : 0.f;
            float e20 = vA ? expf(Lg[d0 + 8 * mstep + pA] - mxA) * ivA : 0.f;
            float e21 = vA ? expf(Lg[d0 + 9 * mstep + pA] - mxA) * ivA : 0.f;
            float e30 = vB ? expf(Lg[d0 + 8 * mstep + pB] - mxB) * ivB : 0.f;
            float e31 = vB ? expf(Lg[d0 + 9 * mstep + pB] - mxB) * ivB : 0.f;
            pksp(e00, e01, dah[0], dal[0]);
            pksp(e10, e11, dah[1], dal[1]);
            pksp(e20, e21, dah[2], dal[2]);
            pksp(e30, e31, dah[3], dal[3]);
        }
        uint32_t cah[4], cal[4];
        {
            const long long c0r = ((long long)(b * Mt + gid) * Ne + n) * Hh;
            const long long c8r = c0r + 8 * mstep;
            const int k0 = P0 + qid * 2;
            const int k8 = k0 + 8;
            if (k0 + 1 < Hh) {
                cah[0] = *(const uint32_t*)(chh + c0r + k0);
                cal[0] = *(const uint32_t*)(chl + c0r + k0);
                cah[1] = *(const uint32_t*)(chh + c8r + k0);
                cal[1] = *(const uint32_t*)(chl + c8r + k0);
            } else { cah[0] = cal[0] = cah[1] = cal[1] = 0; }
            if (k8 + 1 < Hh) {
                cah[2] = *(const uint32_t*)(chh + c0r + k8);
                cal[2] = *(const uint32_t*)(chl + c0r + k8);
                cah[3] = *(const uint32_t*)(chh + c8r + k8);
                cal[3] = *(const uint32_t*)(chl + c8r + k8);
            } else if (k8 < Hh) {
                uint32_t vh = (uint32_t)*(const uint16_t*)(chh + c0r + k8);
                uint32_t vl = (uint32_t)*(const uint16_t*)(chl + c0r + k8);
                cah[2] = vh; cal[2] = vl;
                vh = (uint32_t)*(const uint16_t*)(chh + c8r + k8);
                vl = (uint32_t)*(const uint16_t*)(chl + c8r + k8);
                cah[3] = vh; cal[3] = vl;
            } else { cah[2] = cal[2] = cah[3] = cal[3] = 0; }
        }

        #pragma unroll
        for (int ti = 0; ti < 11; ++ti) {
            const int tw = w + ti * 8;
            if (tw >= 86) break;
            const int hrow = tw * 8 + gid;
            const uint32_t xh0 = *(const uint32_t*)(sXh + hrow * XH_STR + qid * 2);
            const uint32_t xh1 = *(const uint32_t*)(sXh + hrow * XH_STR + qid * 2 + 8);
            const uint32_t xl0 = *(const uint32_t*)(sXl + hrow * XH_STR + qid * 2);
            const uint32_t xl1 = *(const uint32_t*)(sXl + hrow * XH_STR + qid * 2 + 8);
            float cf[4] = {0.f, 0.f, 0.f, 0.f};
            mma_bf16(cf, dah[0], dah[1], dah[2], dah[3], xh0, xh1);
            mma_bf16(cf, dah[0], dah[1], dah[2], dah[3], xl0, xl1);
            mma_bf16(cf, dal[0], dal[1], dal[2], dal[3], xh0, xh1);
            const int ha = tw * 8 + qid * 2, hb = ha + 1;
            const float ba = sb[ha], bb = sb[hb];
            const float v00 = fmaxf(cf[0] + ba, 0.f);
            const float v01 = fmaxf(cf[1] + bb, 0.f);
            const float v10 = fmaxf(cf[2] + ba, 0.f);
            const float v11 = fmaxf(cf[3] + bb, 0.f);
            bf16 hi, lo;
            split2(v00, hi, lo); sHh[ha * XH_STR + gid]     = hi; sHl[ha * XH_STR + gid]     = lo;
            split2(v01, hi, lo); sHh[hb * XH_STR + gid]     = hi; sHl[hb * XH_STR + gid]     = lo;
            split2(v10, hi, lo); sHh[ha * XH_STR + gid + 8] = hi; sHl[ha * XH_STR + gid + 8] = lo;
            split2(v11, hi, lo); sHh[hb * XH_STR + gid + 8] = hi; sHl[hb * XH_STR + gid + 8] = lo;
        }
        __syncwarp();

        #pragma unroll
        for (int ti = 0; ti < 11; ++ti) {
            const int tw = w + ti * 8;
            if (tw >= 86) break;
            const int hrow = tw * 8 + gid;
            const uint32_t hh0 = *(const uint32_t*)(sHh + hrow * XH_STR + qid * 2);
            const uint32_t hh1 = *(const uint32_t*)(sHh + hrow * XH_STR + qid * 2 + 8);
            const uint32_t hl0 = *(const uint32_t*)(sHl + hrow * XH_STR + qid * 2);
            const uint32_t hl1 = *(const uint32_t*)(sHl + hrow * XH_STR + qid * 2 + 8);
            mma_bf16(acc[ti], cah[0], cah[1], cah[2], cah[3], hh0, hh1);
            mma_bf16(acc[ti], cah[0], cah[1], cah[2], cah[3], hl0, hl1);
            mma_bf16(acc[ti], cal[0], cal[1], cal[2], cal[3], hh0, hh1);
        }
        __syncwarp();
    }

    const long long g0 = ((long long)(b * Mt + gid) * Ne + n) * Hh;
    const long long g8 = g0 + 8 * mstep;
    #pragma unroll
    for (int ti = 0; ti < 11; ++ti) {
        const int tw = w + ti * 8;
        if (tw >= 86) break;
        const int ha = tw * 8 + qid * 2, hb = ha + 1;
        if (ha < Hh) {
            st_split(gh, gl, g0 + ha, acc[ti][0]);
            st_split(gh, gl, g8 + ha, acc[ti][2]);
        }
        if (hb < Hh) {
            st_split(gh, gl, g0 + hb, acc[ti][1]);
            st_split(gh, gl, g8 + hb, acc[ti][3]);
        }
    }
}

// ---------------- output GEMM, Ypart reduction + b2sum folded into the load ----------------
__global__ __launch_bounds__(128) void out_partial(const float* __restrict__ Ypart,
                                                   const float* __restrict__ b2s,
                                                   const float* __restrict__ Wout,
                                                   float* __restrict__ part)
{
    constexpr int KC = (Mt * Dd) / OSPLIT;   // 128
    __shared__ float ys[Bb][KC];
    const int tid = threadIdx.x;
    const int col = tid * 4;
    const int k0  = blockIdx.y * KC;
    const int m   = k0 >> 9;                 // constant per block (KC=128, 512-aligned groups)
    const int d0  = k0 & (OUTD - 1);

    for (int idx = tid; idx < Bb * KC; idx += 128) {
        const int bi = idx >> 7;
        const int kk = idx & (KC - 1);
        const int row = bi * Mt + m;
        float s = b2s[d0 + kk];
        #pragma unroll
        for (int z = 0; z < YSPLIT; ++z)
            s += Ypart[((long long)z * Rows + row) * OUTD + d0 + kk];
        ys[bi][kk] = s;
    }
    __syncthreads();

    float4 acc[Bb];
    #pragma unroll
    for (int bi = 0; bi < Bb; ++bi) acc[bi] = make_float4(0.f,0.f,0.f,0.f);

    for (int kk = 0; kk < KC; ++kk) {
        const float4 w = *(const float4*)(Wout + (long long)(k0 + kk) * OUTD + col);
        #pragma unroll
        for (int bi = 0; bi < Bb; ++bi) {
            const float yv = ys[bi][kk];
            acc[bi].x = fmaf(yv, w.x, acc[bi].x);
            acc[bi].y = fmaf(yv, w.y, acc[bi].y);
            acc[bi].z = fmaf(yv, w.z, acc[bi].z);
            acc[bi].w = fmaf(yv, w.w, acc[bi].w);
        }
    }
    #pragma unroll
    for (int bi = 0; bi < Bb; ++bi)
        *(float4*)(part + ((long long)blockIdx.y * Bb + bi) * OUTD + col) = acc[bi];
}

__global__ void out_reduce(const float* __restrict__ part, const float* __restrict__ bout,
                           float* __restrict__ out)
{
    const int i4 = blockIdx.x * blockDim.x + threadIdx.x;
    const int idx = i4 * 4;
    const int col = idx & (OUTD - 1);
    const int bi  = idx >> 9;
    float4 s = *(const float4*)(bout + col);
    #pragma unroll
    for (int z = 0; z < OSPLIT; ++z) {
        float4 p = *(const float4*)(part + ((long long)z * Bb + bi) * OUTD + col);
        s.x += p.x; s.y += p.y; s.z += p.z; s.w += p.w;
    }
    *(float4*)(out + idx) = s;
}

// ---------------- launch ----------------
extern "C" void kernel_launch(void* const* d_in, const int* in_sizes, int n_in,
                              void* d_out, int out_size)
{
    const float* x    = (const float*)d_in[0];
    const float* phi  = (const float*)d_in[1];
    const float* W1   = (const float*)d_in[2];
    const float* b1   = (const float*)d_in[3];
    const float* W2   = (const float*)d_in[4];
    const float* b2   = (const float*)d_in[5];
    const float* Wout = (const float*)d_in[6];
    const float* bout = (const float*)d_in[7];
    float* out = (float*)d_out;

    float *p_logits, *p_XW1, *p_Ypart, *p_b2sum, *p_opart;
    bf16 *p_xh, *p_xl, *p_gh, *p_gl, *p_chh, *p_chl;
    cudaGetSymbolAddress((void**)&p_logits, g_logits);
    cudaGetSymbolAddress((void**)&p_XW1,    g_XW1);
    cudaGetSymbolAddress((void**)&p_Ypart,  g_Ypart);
    cudaGetSymbolAddress((void**)&p_b2sum,  g_b2sum);
    cudaGetSymbolAddress((void**)&p_opart,  g_opart);
    cudaGetSymbolAddress((void**)&p_xh,   g_xh);
    cudaGetSymbolAddress((void**)&p_xl,   g_xl);
    cudaGetSymbolAddress((void**)&p_gh,   g_gh);
    cudaGetSymbolAddress((void**)&p_gl,   g_gl);
    cudaGetSymbolAddress((void**)&p_chh,  g_chh);
    cudaGetSymbolAddress((void**)&p_chl,  g_chl);

    cudaFuncSetAttribute(dual_gemm,  cudaFuncAttributeMaxDynamicSharedMemorySize, MG_SMEM);
    cudaFuncSetAttribute(y_gemm,     cudaFuncAttributeMaxDynamicSharedMemorySize, MG_SMEM);
    cudaFuncSetAttribute(fused_G_tc, cudaFuncAttributeMaxDynamicSharedMemorySize, FG_SMEM);

    prep_k<<<CVT_BLOCKS + 2, 256>>>(x, p_xh, p_xl, b2, p_b2sum);

    const dim3 gDual((NHt + 63)/64, Rows/128, 2);            // 171 x 2 x 2
    dual_gemm<<<gDual, 256, MG_SMEM>>>(p_xh, p_xl, phi, W1, p_logits, p_XW1);

    softmax_np<<<Rows, 256>>>(p_logits, p_chh, p_chl);

    fused_G_tc<<<Bb*Ne, 256, FG_SMEM>>>(p_XW1, p_logits, p_chh, p_chl, b1, p_gh, p_gl);

    const dim3 gY(OUTD/64, Rows/128, YSPLIT);                // 8 x 2 x 16
    y_gemm<<<gY, 256, MG_SMEM>>>(p_gh, p_gl, W2, p_Ypart);

    const dim3 gO(1, OSPLIT, 1);
    out_partial<<<gO, 128>>>(p_Ypart, p_b2sum, Wout, p_opart);
    out_reduce <<<(Bb*OUTD/4)/256, 256>>>(p_opart, bout, out);
}

// round 11
// speedup vs baseline: 1.4008x; 1.4008x over previous
#include <cuda_runtime.h>
#include <cuda_bf16.h>
#include <math.h>
#include <stdint.h>

#define Bb   16
#define Mt   16
#define Dd   512
#define Ne   16
#define Hh   682
#define NHt  (Ne*Hh)      /* 10912 */
#define Rows (Bb*Mt)      /* 256   */
#define OUTD 512
#define YSPLIT 16
#define OSPLIT 64

typedef unsigned long long ull;
typedef __nv_bfloat16 bf16;

// ---- warp mma: D(16x8 f32) += A(16x16 bf16) * B(16x8 bf16) ----
__device__ __forceinline__ void mma_bf16(float* c, uint32_t a0, uint32_t a1, uint32_t a2, uint32_t a3,
                                         uint32_t b0, uint32_t b1) {
    asm volatile("mma.sync.aligned.m16n8k16.row.col.f32.bf16.bf16.f32 "
        "{%0,%1,%2,%3}, {%4,%5,%6,%7}, {%8,%9}, {%0,%1,%2,%3};"
        : "+f"(c[0]), "+f"(c[1]), "+f"(c[2]), "+f"(c[3])
        : "r"(a0), "r"(a1), "r"(a2), "r"(a3), "r"(b0), "r"(b1));
}

__device__ __forceinline__ void split2(float v, bf16& h, bf16& l) {
    h = __float2bfloat16(v);
    l = __float2bfloat16(v - __bfloat162float(h));
}
__device__ __forceinline__ void st_split(bf16* gh, bf16* gl, long long idx, float v) {
    bf16 h, l; split2(v, h, l);
    gh[idx] = h; gl[idx] = l;
}
__device__ __forceinline__ void pksp(float x, float y, uint32_t& hr, uint32_t& lr) {
    bf16 hx, lx, hy, ly;
    split2(x, hx, lx); split2(y, hy, ly);
    __nv_bfloat162 H; H.x = hx; H.y = hy;
    __nv_bfloat162 L; L.x = lx; L.y = ly;
    hr = *(uint32_t*)&H; lr = *(uint32_t*)&L;
}

// ---------------- scratch ----------------
__device__ float g_logits[Rows*NHt];
__device__ float g_XW1[Rows*NHt];
__device__ float g_Ypart[YSPLIT*Rows*OUTD];
__device__ float g_Y[Rows*OUTD];
__device__ float g_b2sum[OUTD];
__device__ float g_opart[OSPLIT*Bb*OUTD];
__device__ bf16 g_xh[Rows*Dd],  g_xl[Rows*Dd];
__device__ bf16 g_gh[Rows*NHt], g_gl[Rows*NHt];
__device__ bf16 g_chh[Rows*NHt], g_chl[Rows*NHt];

// ---------------- prep: x split + b2sum ----------------
#define CVT_BLOCKS (Rows*Dd/4/256)      /* 128 */
__global__ void prep_k(const float* __restrict__ src, bf16* __restrict__ hi,
                       bf16* __restrict__ lo, const float* __restrict__ b2,
                       float* __restrict__ b2s)
{
    const int bx = blockIdx.x;
    if (bx < CVT_BLOCKS) {
        const int i = bx * 256 + threadIdx.x;
        const float4 v = ((const float4*)src)[i];
        bf16 h[4], l[4];
        const float vv[4] = {v.x, v.y, v.z, v.w};
        #pragma unroll
        for (int e = 0; e < 4; ++e) split2(vv[e], h[e], l[e]);
        *(ull*)(hi + i * 4) = *(const ull*)h;
        *(ull*)(lo + i * 4) = *(const ull*)l;
    } else {
        const int d = (bx - CVT_BLOCKS) * 256 + threadIdx.x;
        if (d < OUTD) {
            float s = 0.f;
            #pragma unroll
            for (int n = 0; n < Ne; ++n) s += b2[n * OUTD + d];
            b2s[d] = s;
        }
    }
}

// ---------------- mma.sync bf16-split GEMM (R9 proven version) ----------------
#define AS_STR 72
#define BS_STR 74
#define SM_AH 0
#define SM_AL (SM_AH + 128*AS_STR*2)
#define SM_BH (SM_AL + 128*AS_STR*2)
#define SM_BL (SM_BH + 64*BS_STR*2)
#define MG_SMEM (SM_BL + 64*BS_STR*2)    /* 55808 */

template<int MODE>
__global__ __launch_bounds__(256) void mma_gemm(
    const bf16* __restrict__ Ah, const bf16* __restrict__ Al,
    const float* __restrict__ Bm,
    float* __restrict__ C, int Nc, int K, int nsplit)
{
    extern __shared__ __align__(16) char sm[];
    bf16* sAh = (bf16*)(sm + SM_AH);
    bf16* sAl = (bf16*)(sm + SM_AL);
    bf16* sBh = (bf16*)(sm + SM_BH);
    bf16* sBl = (bf16*)(sm + SM_BL);

    const int t = threadIdx.x;
    const int lane = t & 31, warp = t >> 5;
    const int wm = (warp & 3) * 32;
    const int wn = (warp >> 2) * 32;
    const int m0 = blockIdx.y * 128;
    const int j0 = blockIdx.x * 64;
    const int z  = blockIdx.z;
    const int nch = (K + 63) >> 6;
    const int c0 = (int)((long long)nch * z / nsplit);
    const int c1 = (int)((long long)nch * (z + 1) / nsplit);

    float acc[2][4][4];
    #pragma unroll
    for (int i = 0; i < 2; ++i)
        #pragma unroll
        for (int j = 0; j < 4; ++j)
            #pragma unroll
            for (int e = 0; e < 4; ++e) acc[i][j][e] = 0.f;

    const int gid = lane >> 2;
    const int qid = lane & 3;

    int bn[4], bh[4];
    if (MODE == 1) {
        #pragma unroll
        for (int it = 0; it < 4; ++it) {
            const int g = (t + it * 256) & 15;
            const int j = j0 + g * 4;
            int n = j / Hh;
            bn[it] = n;
            bh[it] = j - n * Hh;
        }
    }

    for (int c = c0; c < c1; ++c) {
        const int k0 = c << 6;
        __syncthreads();
        #pragma unroll
        for (int it = 0; it < 8; ++it) {
            const int s = t + it * 256;
            const int kq = s & 15;
            const int row = s >> 4;
            const int gk = k0 + kq * 4;
            const long long ga = (long long)(m0 + row) * K + gk;
            ull vh = 0, vl = 0;
            if (gk + 4 <= K) { vh = *(const ull*)(Ah + ga); vl = *(const ull*)(Al + ga); }
            *(ull*)(sAh + row * AS_STR + kq * 4) = vh;
            *(ull*)(sAl + row * AS_STR + kq * 4) = vl;
        }
        #pragma unroll
        for (int it = 0; it < 4; ++it) {
            const int s = t + it * 256;
            const int g = s & 15;
            const int k = s >> 4;
            const int gj = j0 + g * 4;
            const int gk = k0 + k;
            float vv[4] = {0.f, 0.f, 0.f, 0.f};
            if (MODE == 0) {
                if (gj + 4 <= Nc && gk < K) {
                    const float4 v = *(const float4*)(Bm + (long long)gk * Nc + gj);
                    vv[0] = v.x; vv[1] = v.y; vv[2] = v.z; vv[3] = v.w;
                }
            } else {
                if (gk < K) {
                    int n = bn[it], h = bh[it];
                    #pragma unroll
                    for (int e = 0; e < 4; ++e) {
                        if (gj + e < Nc) vv[e] = Bm[((long long)n * K + gk) * Hh + h];
                        if (++h >= Hh) { h = 0; ++n; }
                    }
                }
            }
            #pragma unroll
            for (int e = 0; e < 4; ++e) {
                bf16 h, l; split2(vv[e], h, l);
                sBh[(g * 4 + e) * BS_STR + k] = h;
                sBl[(g * 4 + e) * BS_STR + k] = l;
            }
        }
        __syncthreads();

        #pragma unroll
        for (int ks = 0; ks < 4; ++ks) {
            const int kcol = ks * 16 + qid * 2;
            uint32_t ah[2][4], al[2][4];
            #pragma unroll
            for (int mi = 0; mi < 2; ++mi) {
                const int r = wm + mi * 16 + gid;
                ah[mi][0] = *(const uint32_t*)(sAh + r * AS_STR + kcol);
                ah[mi][1] = *(const uint32_t*)(sAh + (r + 8) * AS_STR + kcol);
                ah[mi][2] = *(const uint32_t*)(sAh + r * AS_STR + kcol + 8);
                ah[mi][3] = *(const uint32_t*)(sAh + (r + 8) * AS_STR + kcol + 8);
                al[mi][0] = *(const uint32_t*)(sAl + r * AS_STR + kcol);
                al[mi][1] = *(const uint32_t*)(sAl + (r + 8) * AS_STR + kcol);
                al[mi][2] = *(const uint32_t*)(sAl + r * AS_STR + kcol + 8);
                al[mi][3] = *(const uint32_t*)(sAl + (r + 8) * AS_STR + kcol + 8);
            }
            uint32_t bhf[4][2], blf[4][2];
            #pragma unroll
            for (int ni = 0; ni < 4; ++ni) {
                const int n = wn + ni * 8 + gid;
                bhf[ni][0] = *(const uint32_t*)(sBh + n * BS_STR + kcol);
                bhf[ni][1] = *(const uint32_t*)(sBh + n * BS_STR + kcol + 8);
                blf[ni][0] = *(const uint32_t*)(sBl + n * BS_STR + kcol);
                blf[ni][1] = *(const uint32_t*)(sBl + n * BS_STR + kcol + 8);
            }
            #pragma unroll
            for (int mi = 0; mi < 2; ++mi)
                #pragma unroll
                for (int ni = 0; ni < 4; ++ni) {
                    mma_bf16(acc[mi][ni], ah[mi][0], ah[mi][1], ah[mi][2], ah[mi][3],
                             bhf[ni][0], bhf[ni][1]);
                    mma_bf16(acc[mi][ni], ah[mi][0], ah[mi][1], ah[mi][2], ah[mi][3],
                             blf[ni][0], blf[ni][1]);
                    mma_bf16(acc[mi][ni], al[mi][0], al[mi][1], al[mi][2], al[mi][3],
                             bhf[ni][0], bhf[ni][1]);
                }
        }
    }

    float* Cz = C + (long long)z * Rows * Nc;
    #pragma unroll
    for (int mi = 0; mi < 2; ++mi) {
        const int r0 = m0 + wm + mi * 16 + gid;
        #pragma unroll
        for (int ni = 0; ni < 4; ++ni) {
            const int cn = j0 + wn + ni * 8 + qid * 2;
            if (cn < Nc) {
                float2 lo2 = make_float2(acc[mi][ni][0], acc[mi][ni][1]);
                float2 hi2 = make_float2(acc[mi][ni][2], acc[mi][ni][3]);
                *(float2*)(Cz + (long long)r0 * Nc + cn)       = lo2;
                *(float2*)(Cz + (long long)(r0 + 8) * Nc + cn) = hi2;
            }
        }
    }
}

// ---------------- softmax_np -> Cw bf16 hi/lo ----------------
__global__ void softmax_np(const float* __restrict__ L, bf16* __restrict__ chh,
                           bf16* __restrict__ chl)
{
    __shared__ float s[Ne * 688];
    const int bm  = blockIdx.x;
    const int tid = threadIdx.x;
    const float* Lrow = L + bm * NHt;

    for (int i4 = tid; i4 < NHt / 4; i4 += 256) {
        const float4 v = *(const float4*)(Lrow + i4 * 4);
        const int idx = i4 * 4;
        const int n = idx / Hh;
        const int p = idx - n * Hh;
        float vv[4] = {v.x, v.y, v.z, v.w};
        int nn = n, pp = p;
        #pragma unroll
        for (int e = 0; e < 4; ++e) {
            s[nn * 688 + pp] = vv[e];
            if (++pp >= Hh) { pp = 0; ++nn; }
        }
    }
    __syncthreads();

    for (int p = tid; p < Hh; p += 256) {
        float mx = -3.4e38f;
        #pragma unroll
        for (int n = 0; n < Ne; ++n) mx = fmaxf(mx, s[n * 688 + p]);
        float sum = 0.f;
        #pragma unroll
        for (int n = 0; n < Ne; ++n) {
            const float e = expf(s[n * 688 + p] - mx);
            s[n * 688 + p] = e;
            sum += e;
        }
        const float inv = 1.f / sum;
        #pragma unroll
        for (int n = 0; n < Ne; ++n) s[n * 688 + p] *= inv;
    }
    __syncthreads();

    const int warp = tid >> 5, lane = tid & 31;
    for (int n = warp; n < Ne; n += 8) {
        float mx = -3.4e38f;
        for (int p = lane; p < Hh; p += 32) mx = fmaxf(mx, s[n * 688 + p]);
        #pragma unroll
        for (int o = 16; o; o >>= 1) mx = fmaxf(mx, __shfl_xor_sync(0xffffffffu, mx, o));
        float sum = 0.f;
        for (int p = lane; p < Hh; p += 32) {
            const float e = expf(s[n * 688 + p] - mx);
            s[n * 688 + p] = e;
            sum += e;
        }
        #pragma unroll
        for (int o = 16; o; o >>= 1) sum += __shfl_xor_sync(0xffffffffu, sum, o);
        const float inv = 1.f / sum;
        for (int p = lane; p < Hh; p += 32) {
            bf16 h, l; split2(s[n * 688 + p] * inv, h, l);
            const long long o2 = (long long)bm * NHt + n * Hh + p;
            chh[o2] = h; chl[o2] = l;
        }
    }
}

// ---------------- TENSOR fused, h-SPLIT x2: 2 blocks per (b,n) ----------------
// block handles h-tiles tw_local in [0,43) => h in [half*344, half*344+344)
#define XH_STR 18
#define HLEN 352
#define FG_SXH 0
#define FG_SXL (FG_SXH + HLEN*XH_STR*2)
#define FG_SHH (FG_SXL + HLEN*XH_STR*2)
#define FG_SHL (FG_SHH + HLEN*XH_STR*2)
#define FG_SB   (FG_SHL + HLEN*XH_STR*2)   /* 50688 */
#define FG_SMX  (FG_SB  + HLEN*4)          /* 52096 */
#define FG_SINV (FG_SMX + 688*4)           /* 54848 */
#define FG_SMEM (FG_SINV + 688*4)          /* 57600 */
#define NTILE 43

__global__ __launch_bounds__(256) void fused_G_tc(const float* __restrict__ XW1,
                                                  const float* __restrict__ Lg,
                                                  const bf16* __restrict__ chh,
                                                  const bf16* __restrict__ chl,
                                                  const float* __restrict__ b1,
                                                  bf16* __restrict__ gh,
                                                  bf16* __restrict__ gl)
{
    extern __shared__ __align__(16) char sm[];
    bf16*  sXh = (bf16*)(sm + FG_SXH);
    bf16*  sXl = (bf16*)(sm + FG_SXL);
    bf16*  sHh = (bf16*)(sm + FG_SHH);
    bf16*  sHl = (bf16*)(sm + FG_SHL);
    float* sb   = (float*)(sm + FG_SB);
    float* smx  = (float*)(sm + FG_SMX);
    float* sinv = (float*)(sm + FG_SINV);

    const int bx = blockIdx.x;
    const int half = bx & 1;
    const int n  = (bx >> 1) & (Ne - 1);
    const int b  = bx >> 5;
    const int h0g = half * 344;               // global h base for this block
    const int t = threadIdx.x;
    const int w = t >> 5, lane = t & 31;
    const int gid = lane >> 2, qid = lane & 3;
    const long long mstep = (long long)NHt;

    // ---- Dw softmax stats over full p range (needed by every chunk)
    for (int p = t; p < 688; p += 256) {
        if (p < Hh) {
            const long long base = ((long long)(b * Mt) * Ne + n) * Hh + p;
            float v[Mt], mx = -3.4e38f;
            #pragma unroll
            for (int m = 0; m < Mt; ++m) { v[m] = Lg[base + m * mstep]; mx = fmaxf(mx, v[m]); }
            float sum = 0.f;
            #pragma unroll
            for (int m = 0; m < Mt; ++m) sum += expf(v[m] - mx);
            smx[p] = mx; sinv[p] = 1.f / sum;
        } else { smx[p] = 0.f; sinv[p] = 0.f; }
    }
    // ---- local bias
    for (int hl = t; hl < HLEN; hl += 256) {
        const int h = h0g + hl;
        sb[hl] = (hl < 344 && h < Hh) ? b1[n * Hh + h] : 0.f;
    }

    // ---- stage local XW1 slice -> sX[hl][m] bf16 hi/lo
    #pragma unroll 1
    for (int mm = 0; mm < Mt; ++mm) {
        const long long rb = ((long long)(b * Mt + mm) * Ne + n) * Hh;
        for (int hl = t; hl < HLEN; hl += 256) {
            const int h = h0g + hl;
            const float v = (hl < 344 && h < Hh) ? XW1[rb + h] : 0.f;
            bf16 hi, lo; split2(v, hi, lo);
            sXh[hl * XH_STR + mm] = hi;
            sXl[hl * XH_STR + mm] = lo;
        }
    }
    __syncthreads();

    float acc[6][4];
    #pragma unroll
    for (int i = 0; i < 6; ++i)
        #pragma unroll
        for (int e = 0; e < 4; ++e) acc[i][e] = 0.f;

    const int NCH = (Hh + 15) / 16;  // 43 p-chunks

    for (int c = 0; c < NCH; ++c) {
        const int P0 = c * 16;
        // ---- Dw A-fragments (full p) from logits + stats
        const int pA = P0 + gid, pB = pA + 8;
        const bool vA = (pA < Hh), vB = (pB < Hh);
        const int m0 = qid * 2;
        const long long d0 = ((long long)(b * Mt + m0) * Ne + n) * Hh;
        const float mxA = smx[pA], ivA = sinv[pA];
        const float mxB = smx[pB], ivB = sinv[pB];
        uint32_t dah[4], dal[4];
        {
            float e00 = vA ? expf(Lg[d0 + pA]             - mxA) * ivA : 0.f;
            float e01 = vA ? expf(Lg[d0 + mstep + pA]     - mxA) * ivA : 0.f;
            float e10 = vB ? expf(Lg[d0 + pB]             - mxB) * ivB : 0.f;
            float e11 = vB ? expf(Lg[d0 + mstep + pB]     - mxB) * ivB : 0.f;
            float e20 = vA ? expf(Lg[d0 + 8 * mstep + pA] - mxA) * ivA : 0.f;
            float e21 = vA ? expf(Lg[d0 + 9 * mstep + pA] - mxA) * ivA : 0.f;
            float e30 = vB ? expf(Lg[d0 + 8 * mstep + pB] - mxB) * ivB : 0.f;
            float e31 = vB ? expf(Lg[d0 + 9 * mstep + pB] - mxB) * ivB : 0.f;
            pksp(e00, e01, dah[0], dal[0]);
            pksp(e10, e11, dah[1], dal[1]);
            pksp(e20, e21, dah[2], dal[2]);
            pksp(e30, e31, dah[3], dal[3]);
        }
        // ---- Cw A-fragments: direct loads from pre-split bf16
        uint32_t cah[4], cal[4];
        {
            const long long c0r = ((long long)(b * Mt + gid) * Ne + n) * Hh;
            const long long c8r = c0r + 8 * mstep;
            const int k0 = P0 + qid * 2;
            const int k8 = k0 + 8;
            if (k0 + 1 < Hh) {
                cah[0] = *(const uint32_t*)(chh + c0r + k0);
                cal[0] = *(const uint32_t*)(chl + c0r + k0);
                cah[1] = *(const uint32_t*)(chh + c8r + k0);
                cal[1] = *(const uint32_t*)(chl + c8r + k0);
            } else { cah[0] = cal[0] = cah[1] = cal[1] = 0; }
            if (k8 + 1 < Hh) {
                cah[2] = *(const uint32_t*)(chh + c0r + k8);
                cal[2] = *(const uint32_t*)(chl + c0r + k8);
                cah[3] = *(const uint32_t*)(chh + c8r + k8);
                cal[3] = *(const uint32_t*)(chl + c8r + k8);
            } else if (k8 < Hh) {
                uint32_t vh = (uint32_t)*(const uint16_t*)(chh + c0r + k8);
                uint32_t vl = (uint32_t)*(const uint16_t*)(chl + c0r + k8);
                cah[2] = vh; cal[2] = vl;
                vh = (uint32_t)*(const uint16_t*)(chh + c8r + k8);
                vl = (uint32_t)*(const uint16_t*)(chl + c8r + k8);
                cah[3] = vh; cal[3] = vl;
            } else { cah[2] = cal[2] = cah[3] = cal[3] = 0; }
        }

        // ---- stage 1: H = Dw^T @ XW1, +bias, relu -> sH[hl][p]
        #pragma unroll
        for (int ti = 0; ti < 6; ++ti) {
            const int twl = w + ti * 8;
            if (twl >= NTILE) break;
            const int hrow = twl * 8 + gid;
            const uint32_t xh0 = *(const uint32_t*)(sXh + hrow * XH_STR + qid * 2);
            const uint32_t xh1 = *(const uint32_t*)(sXh + hrow * XH_STR + qid * 2 + 8);
            const uint32_t xl0 = *(const uint32_t*)(sXl + hrow * XH_STR + qid * 2);
            const uint32_t xl1 = *(const uint32_t*)(sXl + hrow * XH_STR + qid * 2 + 8);
            float cf[4] = {0.f, 0.f, 0.f, 0.f};
            mma_bf16(cf, dah[0], dah[1], dah[2], dah[3], xh0, xh1);
            mma_bf16(cf, dah[0], dah[1], dah[2], dah[3], xl0, xl1);
            mma_bf16(cf, dal[0], dal[1], dal[2], dal[3], xh0, xh1);
            const int ha = twl * 8 + qid * 2, hb = ha + 1;
            const float ba = sb[ha], bb = sb[hb];
            const float v00 = fmaxf(cf[0] + ba, 0.f);
            const float v01 = fmaxf(cf[1] + bb, 0.f);
            const float v10 = fmaxf(cf[2] + ba, 0.f);
            const float v11 = fmaxf(cf[3] + bb, 0.f);
            bf16 hi, lo;
            split2(v00, hi, lo); sHh[ha * XH_STR + gid]     = hi; sHl[ha * XH_STR + gid]     = lo;
            split2(v01, hi, lo); sHh[hb * XH_STR + gid]     = hi; sHl[hb * XH_STR + gid]     = lo;
            split2(v10, hi, lo); sHh[ha * XH_STR + gid + 8] = hi; sHl[ha * XH_STR + gid + 8] = lo;
            split2(v11, hi, lo); sHh[hb * XH_STR + gid + 8] = hi; sHl[hb * XH_STR + gid + 8] = lo;
        }
        __syncwarp();

        // ---- stage 2: G += Cw_chunk @ H_chunk
        #pragma unroll
        for (int ti = 0; ti < 6; ++ti) {
            const int twl = w + ti * 8;
            if (twl >= NTILE) break;
            const int hrow = twl * 8 + gid;
            const uint32_t hh0 = *(const uint32_t*)(sHh + hrow * XH_STR + qid * 2);
            const uint32_t hh1 = *(const uint32_t*)(sHh + hrow * XH_STR + qid * 2 + 8);
            const uint32_t hl0 = *(const uint32_t*)(sHl + hrow * XH_STR + qid * 2);
            const uint32_t hl1 = *(const uint32_t*)(sHl + hrow * XH_STR + qid * 2 + 8);
            mma_bf16(acc[ti], cah[0], cah[1], cah[2], cah[3], hh0, hh1);
            mma_bf16(acc[ti], cah[0], cah[1], cah[2], cah[3], hl0, hl1);
            mma_bf16(acc[ti], cal[0], cal[1], cal[2], cal[3], hh0, hh1);
        }
        __syncwarp();
    }

    // ---- store G (bf16 hi/lo)
    const long long g0 = ((long long)(b * Mt + gid) * Ne + n) * Hh;
    const long long g8 = g0 + 8 * mstep;
    #pragma unroll
    for (int ti = 0; ti < 6; ++ti) {
        const int twl = w + ti * 8;
        if (twl >= NTILE) break;
        const int ha = h0g + twl * 8 + qid * 2, hb = ha + 1;
        if (ha < Hh) {
            st_split(gh, gl, g0 + ha, acc[ti][0]);
            st_split(gh, gl, g8 + ha, acc[ti][2]);
        }
        if (hb < Hh) {
            st_split(gh, gl, g0 + hb, acc[ti][1]);
            st_split(gh, gl, g8 + hb, acc[ti][3]);
        }
    }
}

// ---------------- ypart_reduce ----------------
__global__ void ypart_reduce(const float* __restrict__ part, const float* __restrict__ b2s,
                             float* __restrict__ Y)
{
    const int i4 = blockIdx.x * blockDim.x + threadIdx.x;
    const int idx = i4 * 4;
    const int col = idx & (OUTD - 1);
    float4 s = *(const float4*)(b2s + col);
    #pragma unroll
    for (int z = 0; z < YSPLIT; ++z) {
        float4 p = *(const float4*)(part + z * (Rows * OUTD) + idx);
        s.x += p.x; s.y += p.y; s.z += p.z; s.w += p.w;
    }
    *(float4*)(Y + idx) = s;
}

// ---------------- output GEMM ----------------
__global__ __launch_bounds__(128) void out_partial(const float* __restrict__ Y,
                                                   const float* __restrict__ Wout,
                                                   float* __restrict__ part)
{
    constexpr int KC = (Mt * Dd) / OSPLIT;
    __shared__ float ys[Bb][KC];
    const int tid = threadIdx.x;
    const int col = tid * 4;
    const int k0  = blockIdx.y * KC;

    for (int idx = tid; idx < Bb * KC; idx += 128) {
        const int bi = idx / KC, kk = idx - bi * KC;
        ys[bi][kk] = Y[bi * (Mt * Dd) + k0 + kk];
    }
    __syncthreads();

    float4 acc[Bb];
    #pragma unroll
    for (int bi = 0; bi < Bb; ++bi) acc[bi] = make_float4(0.f,0.f,0.f,0.f);

    for (int kk = 0; kk < KC; ++kk) {
        const float4 w = *(const float4*)(Wout + (k0 + kk) * OUTD + col);
        #pragma unroll
        for (int bi = 0; bi < Bb; ++bi) {
            const float yv = ys[bi][kk];
            acc[bi].x = fmaf(yv, w.x, acc[bi].x);
            acc[bi].y = fmaf(yv, w.y, acc[bi].y);
            acc[bi].z = fmaf(yv, w.z, acc[bi].z);
            acc[bi].w = fmaf(yv, w.w, acc[bi].w);
        }
    }
    #pragma unroll
    for (int bi = 0; bi < Bb; ++bi)
        *(float4*)(part + (blockIdx.y * Bb + bi) * OUTD + col) = acc[bi];
}

__global__ void out_reduce(const float* __restrict__ part, const float* __restrict__ bout,
                           float* __restrict__ out)
{
    const int i4 = blockIdx.x * blockDim.x + threadIdx.x;
    const int idx = i4 * 4;
    const int col = idx & (OUTD - 1);
    const int bi  = idx >> 9;
    float4 s = *(const float4*)(bout + col);
    #pragma unroll
    for (int z = 0; z < OSPLIT; ++z) {
        float4 p = *(const float4*)(part + (z * Bb + bi) * OUTD + col);
        s.x += p.x; s.y += p.y; s.z += p.z; s.w += p.w;
    }
    *(float4*)(out + idx) = s;
}

// ---------------- launch ----------------
extern "C" void kernel_launch(void* const* d_in, const int* in_sizes, int n_in,
                              void* d_out, int out_size)
{
    const float* x    = (const float*)d_in[0];
    const float* phi  = (const float*)d_in[1];
    const float* W1   = (const float*)d_in[2];
    const float* b1   = (const float*)d_in[3];
    const float* W2   = (const float*)d_in[4];
    const float* b2   = (const float*)d_in[5];
    const float* Wout = (const float*)d_in[6];
    const float* bout = (const float*)d_in[7];
    float* out = (float*)d_out;

    float *p_logits, *p_XW1, *p_Ypart, *p_Y, *p_b2sum, *p_opart;
    bf16 *p_xh, *p_xl, *p_gh, *p_gl, *p_chh, *p_chl;
    cudaGetSymbolAddress((void**)&p_logits, g_logits);
    cudaGetSymbolAddress((void**)&p_XW1,    g_XW1);
    cudaGetSymbolAddress((void**)&p_Ypart,  g_Ypart);
    cudaGetSymbolAddress((void**)&p_Y,      g_Y);
    cudaGetSymbolAddress((void**)&p_b2sum,  g_b2sum);
    cudaGetSymbolAddress((void**)&p_opart,  g_opart);
    cudaGetSymbolAddress((void**)&p_xh,   g_xh);
    cudaGetSymbolAddress((void**)&p_xl,   g_xl);
    cudaGetSymbolAddress((void**)&p_gh,   g_gh);
    cudaGetSymbolAddress((void**)&p_gl,   g_gl);
    cudaGetSymbolAddress((void**)&p_chh,  g_chh);
    cudaGetSymbolAddress((void**)&p_chl,  g_chl);

    cudaFuncSetAttribute(mma_gemm<0>, cudaFuncAttributeMaxDynamicSharedMemorySize, MG_SMEM);
    cudaFuncSetAttribute(mma_gemm<1>, cudaFuncAttributeMaxDynamicSharedMemorySize, MG_SMEM);
    cudaFuncSetAttribute(fused_G_tc,  cudaFuncAttributeMaxDynamicSharedMemorySize, FG_SMEM);

    prep_k<<<CVT_BLOCKS + 2, 256>>>(x, p_xh, p_xl, b2, p_b2sum);

    const dim3 gBig((NHt + 63)/64, Rows/128, 1);             // 171 x 2
    mma_gemm<0><<<gBig, 256, MG_SMEM>>>(p_xh, p_xl, phi, p_logits, NHt, Dd, 1);
    mma_gemm<1><<<gBig, 256, MG_SMEM>>>(p_xh, p_xl, W1,  p_XW1,    NHt, Dd, 1);

    softmax_np<<<Rows, 256>>>(p_logits, p_chh, p_chl);

    fused_G_tc<<<Bb*Ne*2, 256, FG_SMEM>>>(p_XW1, p_logits, p_chh, p_chl, b1, p_gh, p_gl);

    const dim3 gY(OUTD/64, Rows/128, YSPLIT);                // 8 x 2 x 16
    mma_gemm<0><<<gY, 256, MG_SMEM>>>(p_gh, p_gl, W2, p_Ypart, OUTD, NHt, YSPLIT);
    ypart_reduce<<<(Rows*OUTD/4)/256, 256>>>(p_Ypart, p_b2sum, p_Y);

    const dim3 gO(1, OSPLIT, 1);
    out_partial<<<gO, 128>>>(p_Y, Wout, p_opart);
    out_reduce <<<(Bb*OUTD/4)/256, 256>>>(p_opart, bout, out);
}

// round 12
// speedup vs baseline: 1.5074x; 1.0761x over previous
#include <cuda_runtime.h>
#include <cuda_bf16.h>
#include <math.h>
#include <stdint.h>

#define Bb   16
#define Mt   16
#define Dd   512
#define Ne   16
#define Hh   682
#define HhP  688          /* padded p extent */
#define NHt  (Ne*Hh)      /* 10912 */
#define Rows (Bb*Mt)      /* 256   */
#define OUTD 512
#define YSPLIT 16
#define OSPLIT 64

typedef unsigned long long ull;
typedef __nv_bfloat16 bf16;

// ---- warp mma: D(16x8 f32) += A(16x16 bf16) * B(16x8 bf16) ----
__device__ __forceinline__ void mma_bf16(float* c, uint32_t a0, uint32_t a1, uint32_t a2, uint32_t a3,
                                         uint32_t b0, uint32_t b1) {
    asm volatile("mma.sync.aligned.m16n8k16.row.col.f32.bf16.bf16.f32 "
        "{%0,%1,%2,%3}, {%4,%5,%6,%7}, {%8,%9}, {%0,%1,%2,%3};"
        : "+f"(c[0]), "+f"(c[1]), "+f"(c[2]), "+f"(c[3])
        : "r"(a0), "r"(a1), "r"(a2), "r"(a3), "r"(b0), "r"(b1));
}

__device__ __forceinline__ void split2(float v, bf16& h, bf16& l) {
    h = __float2bfloat16(v);
    l = __float2bfloat16(v - __bfloat162float(h));
}
__device__ __forceinline__ void st_split(bf16* gh, bf16* gl, long long idx, float v) {
    bf16 h, l; split2(v, h, l);
    gh[idx] = h; gl[idx] = l;
}

// ---------------- scratch ----------------
__device__ float g_logits[Rows*NHt];
__device__ float g_XW1[Rows*NHt];
__device__ float g_Ypart[YSPLIT*Rows*OUTD];
__device__ float g_Y[Rows*OUTD];
__device__ float g_b2sum[OUTD];
__device__ float g_opart[OSPLIT*Bb*OUTD];
__device__ bf16 g_xh[Rows*Dd],  g_xl[Rows*Dd];
__device__ bf16 g_gh[Rows*NHt], g_gl[Rows*NHt];
__device__ bf16 g_chh[Rows*NHt], g_chl[Rows*NHt];
__device__ bf16 g_dwh[Bb*Ne*HhP*Mt], g_dwl[Bb*Ne*HhP*Mt];   // Dw^T pre-split [b][n][p][m]

// ---------------- prep: x split + b2sum ----------------
#define CVT_BLOCKS (Rows*Dd/4/256)      /* 128 */
__global__ void prep_k(const float* __restrict__ src, bf16* __restrict__ hi,
                       bf16* __restrict__ lo, const float* __restrict__ b2,
                       float* __restrict__ b2s)
{
    const int bx = blockIdx.x;
    if (bx < CVT_BLOCKS) {
        const int i = bx * 256 + threadIdx.x;
        const float4 v = ((const float4*)src)[i];
        bf16 h[4], l[4];
        const float vv[4] = {v.x, v.y, v.z, v.w};
        #pragma unroll
        for (int e = 0; e < 4; ++e) split2(vv[e], h[e], l[e]);
        *(ull*)(hi + i * 4) = *(const ull*)h;
        *(ull*)(lo + i * 4) = *(const ull*)l;
    } else {
        const int d = (bx - CVT_BLOCKS) * 256 + threadIdx.x;
        if (d < OUTD) {
            float s = 0.f;
            #pragma unroll
            for (int n = 0; n < Ne; ++n) s += b2[n * OUTD + d];
            b2s[d] = s;
        }
    }
}

// ---------------- Dw = softmax over m, transposed + bf16 hi/lo split ----------------
// one thread per (b,n,p) column; output Dwt[b][n][p][m], p padded to 688 with zeros
__global__ void dw_split(const float* __restrict__ Lg, bf16* __restrict__ dwh,
                         bf16* __restrict__ dwl)
{
    const int col = blockIdx.x * 256 + threadIdx.x;   // 0 .. Bb*Ne*HhP-1
    const int p  = col % HhP;
    const int bn = col / HhP;
    const int b  = bn >> 4;
    const int n  = bn & (Ne - 1);

    bf16 h[Mt], l[Mt];
    if (p < Hh) {
        const long long base = ((long long)(b * Mt) * Ne + n) * Hh + p;
        float v[Mt], mx = -3.4e38f;
        #pragma unroll
        for (int m = 0; m < Mt; ++m) { v[m] = Lg[base + (long long)m * NHt]; mx = fmaxf(mx, v[m]); }
        float sum = 0.f;
        #pragma unroll
        for (int m = 0; m < Mt; ++m) { v[m] = expf(v[m] - mx); sum += v[m]; }
        const float inv = 1.f / sum;
        #pragma unroll
        for (int m = 0; m < Mt; ++m) split2(v[m] * inv, h[m], l[m]);
    } else {
        #pragma unroll
        for (int m = 0; m < Mt; ++m) { h[m] = __float2bfloat16(0.f); l[m] = h[m]; }
    }
    const long long o = (long long)col * Mt;
    #pragma unroll
    for (int q = 0; q < 4; ++q) {
        *(ull*)(dwh + o + q * 4) = *(const ull*)(h + q * 4);
        *(ull*)(dwl + o + q * 4) = *(const ull*)(l + q * 4);
    }
}

// ---------------- mma.sync bf16-split GEMM (R9 proven version) ----------------
#define AS_STR 72
#define BS_STR 74
#define SM_AH 0
#define SM_AL (SM_AH + 128*AS_STR*2)
#define SM_BH (SM_AL + 128*AS_STR*2)
#define SM_BL (SM_BH + 64*BS_STR*2)
#define MG_SMEM (SM_BL + 64*BS_STR*2)    /* 55808 */

template<int MODE>
__global__ __launch_bounds__(256) void mma_gemm(
    const bf16* __restrict__ Ah, const bf16* __restrict__ Al,
    const float* __restrict__ Bm,
    float* __restrict__ C, int Nc, int K, int nsplit)
{
    extern __shared__ __align__(16) char sm[];
    bf16* sAh = (bf16*)(sm + SM_AH);
    bf16* sAl = (bf16*)(sm + SM_AL);
    bf16* sBh = (bf16*)(sm + SM_BH);
    bf16* sBl = (bf16*)(sm + SM_BL);

    const int t = threadIdx.x;
    const int lane = t & 31, warp = t >> 5;
    const int wm = (warp & 3) * 32;
    const int wn = (warp >> 2) * 32;
    const int m0 = blockIdx.y * 128;
    const int j0 = blockIdx.x * 64;
    const int z  = blockIdx.z;
    const int nch = (K + 63) >> 6;
    const int c0 = (int)((long long)nch * z / nsplit);
    const int c1 = (int)((long long)nch * (z + 1) / nsplit);

    float acc[2][4][4];
    #pragma unroll
    for (int i = 0; i < 2; ++i)
        #pragma unroll
        for (int j = 0; j < 4; ++j)
            #pragma unroll
            for (int e = 0; e < 4; ++e) acc[i][j][e] = 0.f;

    const int gid = lane >> 2;
    const int qid = lane & 3;

    int bn[4], bh[4];
    if (MODE == 1) {
        #pragma unroll
        for (int it = 0; it < 4; ++it) {
            const int g = (t + it * 256) & 15;
            const int j = j0 + g * 4;
            int n = j / Hh;
            bn[it] = n;
            bh[it] = j - n * Hh;
        }
    }

    for (int c = c0; c < c1; ++c) {
        const int k0 = c << 6;
        __syncthreads();
        #pragma unroll
        for (int it = 0; it < 8; ++it) {
            const int s = t + it * 256;
            const int kq = s & 15;
            const int row = s >> 4;
            const int gk = k0 + kq * 4;
            const long long ga = (long long)(m0 + row) * K + gk;
            ull vh = 0, vl = 0;
            if (gk + 4 <= K) { vh = *(const ull*)(Ah + ga); vl = *(const ull*)(Al + ga); }
            *(ull*)(sAh + row * AS_STR + kq * 4) = vh;
            *(ull*)(sAl + row * AS_STR + kq * 4) = vl;
        }
        #pragma unroll
        for (int it = 0; it < 4; ++it) {
            const int s = t + it * 256;
            const int g = s & 15;
            const int k = s >> 4;
            const int gj = j0 + g * 4;
            const int gk = k0 + k;
            float vv[4] = {0.f, 0.f, 0.f, 0.f};
            if (MODE == 0) {
                if (gj + 4 <= Nc && gk < K) {
                    const float4 v = *(const float4*)(Bm + (long long)gk * Nc + gj);
                    vv[0] = v.x; vv[1] = v.y; vv[2] = v.z; vv[3] = v.w;
                }
            } else {
                if (gk < K) {
                    int n = bn[it], h = bh[it];
                    #pragma unroll
                    for (int e = 0; e < 4; ++e) {
                        if (gj + e < Nc) vv[e] = Bm[((long long)n * K + gk) * Hh + h];
                        if (++h >= Hh) { h = 0; ++n; }
                    }
                }
            }
            #pragma unroll
            for (int e = 0; e < 4; ++e) {
                bf16 h, l; split2(vv[e], h, l);
                sBh[(g * 4 + e) * BS_STR + k] = h;
                sBl[(g * 4 + e) * BS_STR + k] = l;
            }
        }
        __syncthreads();

        #pragma unroll
        for (int ks = 0; ks < 4; ++ks) {
            const int kcol = ks * 16 + qid * 2;
            uint32_t ah[2][4], al[2][4];
            #pragma unroll
            for (int mi = 0; mi < 2; ++mi) {
                const int r = wm + mi * 16 + gid;
                ah[mi][0] = *(const uint32_t*)(sAh + r * AS_STR + kcol);
                ah[mi][1] = *(const uint32_t*)(sAh + (r + 8) * AS_STR + kcol);
                ah[mi][2] = *(const uint32_t*)(sAh + r * AS_STR + kcol + 8);
                ah[mi][3] = *(const uint32_t*)(sAh + (r + 8) * AS_STR + kcol + 8);
                al[mi][0] = *(const uint32_t*)(sAl + r * AS_STR + kcol);
                al[mi][1] = *(const uint32_t*)(sAl + (r + 8) * AS_STR + kcol);
                al[mi][2] = *(const uint32_t*)(sAl + r * AS_STR + kcol + 8);
                al[mi][3] = *(const uint32_t*)(sAl + (r + 8) * AS_STR + kcol + 8);
            }
            uint32_t bhf[4][2], blf[4][2];
            #pragma unroll
            for (int ni = 0; ni < 4; ++ni) {
                const int n = wn + ni * 8 + gid;
                bhf[ni][0] = *(const uint32_t*)(sBh + n * BS_STR + kcol);
                bhf[ni][1] = *(const uint32_t*)(sBh + n * BS_STR + kcol + 8);
                blf[ni][0] = *(const uint32_t*)(sBl + n * BS_STR + kcol);
                blf[ni][1] = *(const uint32_t*)(sBl + n * BS_STR + kcol + 8);
            }
            #pragma unroll
            for (int mi = 0; mi < 2; ++mi)
                #pragma unroll
                for (int ni = 0; ni < 4; ++ni) {
                    mma_bf16(acc[mi][ni], ah[mi][0], ah[mi][1], ah[mi][2], ah[mi][3],
                             bhf[ni][0], bhf[ni][1]);
                    mma_bf16(acc[mi][ni], ah[mi][0], ah[mi][1], ah[mi][2], ah[mi][3],
                             blf[ni][0], blf[ni][1]);
                    mma_bf16(acc[mi][ni], al[mi][0], al[mi][1], al[mi][2], al[mi][3],
                             bhf[ni][0], bhf[ni][1]);
                }
        }
    }

    float* Cz = C + (long long)z * Rows * Nc;
    #pragma unroll
    for (int mi = 0; mi < 2; ++mi) {
        const int r0 = m0 + wm + mi * 16 + gid;
        #pragma unroll
        for (int ni = 0; ni < 4; ++ni) {
            const int cn = j0 + wn + ni * 8 + qid * 2;
            if (cn < Nc) {
                float2 lo2 = make_float2(acc[mi][ni][0], acc[mi][ni][1]);
                float2 hi2 = make_float2(acc[mi][ni][2], acc[mi][ni][3]);
                *(float2*)(Cz + (long long)r0 * Nc + cn)       = lo2;
                *(float2*)(Cz + (long long)(r0 + 8) * Nc + cn) = hi2;
            }
        }
    }
}

// ---------------- softmax_np -> Cw bf16 hi/lo ----------------
__global__ void softmax_np(const float* __restrict__ L, bf16* __restrict__ chh,
                           bf16* __restrict__ chl)
{
    __shared__ float s[Ne * 688];
    const int bm  = blockIdx.x;
    const int tid = threadIdx.x;
    const float* Lrow = L + bm * NHt;

    for (int i4 = tid; i4 < NHt / 4; i4 += 256) {
        const float4 v = *(const float4*)(Lrow + i4 * 4);
        const int idx = i4 * 4;
        const int n = idx / Hh;
        const int p = idx - n * Hh;
        float vv[4] = {v.x, v.y, v.z, v.w};
        int nn = n, pp = p;
        #pragma unroll
        for (int e = 0; e < 4; ++e) {
            s[nn * 688 + pp] = vv[e];
            if (++pp >= Hh) { pp = 0; ++nn; }
        }
    }
    __syncthreads();

    for (int p = tid; p < Hh; p += 256) {
        float mx = -3.4e38f;
        #pragma unroll
        for (int n = 0; n < Ne; ++n) mx = fmaxf(mx, s[n * 688 + p]);
        float sum = 0.f;
        #pragma unroll
        for (int n = 0; n < Ne; ++n) {
            const float e = expf(s[n * 688 + p] - mx);
            s[n * 688 + p] = e;
            sum += e;
        }
        const float inv = 1.f / sum;
        #pragma unroll
        for (int n = 0; n < Ne; ++n) s[n * 688 + p] *= inv;
    }
    __syncthreads();

    const int warp = tid >> 5, lane = tid & 31;
    for (int n = warp; n < Ne; n += 8) {
        float mx = -3.4e38f;
        for (int p = lane; p < Hh; p += 32) mx = fmaxf(mx, s[n * 688 + p]);
        #pragma unroll
        for (int o = 16; o; o >>= 1) mx = fmaxf(mx, __shfl_xor_sync(0xffffffffu, mx, o));
        float sum = 0.f;
        for (int p = lane; p < Hh; p += 32) {
            const float e = expf(s[n * 688 + p] - mx);
            s[n * 688 + p] = e;
            sum += e;
        }
        #pragma unroll
        for (int o = 16; o; o >>= 1) sum += __shfl_xor_sync(0xffffffffu, sum, o);
        const float inv = 1.f / sum;
        for (int p = lane; p < Hh; p += 32) {
            bf16 h, l; split2(s[n * 688 + p] * inv, h, l);
            const long long o2 = (long long)bm * NHt + n * Hh + p;
            chh[o2] = h; chl[o2] = l;
        }
    }
}

// ---------------- TENSOR fused, h-SPLIT x2, Dw pre-split ----------------
#define XH_STR 18
#define HLEN 352
#define FG_SXH 0
#define FG_SXL (FG_SXH + HLEN*XH_STR*2)
#define FG_SHH (FG_SXL + HLEN*XH_STR*2)
#define FG_SHL (FG_SHH + HLEN*XH_STR*2)
#define FG_SB   (FG_SHL + HLEN*XH_STR*2)   /* 50688 */
#define FG_SMEM (FG_SB + HLEN*4)           /* 52096 */
#define NTILE 43

__global__ __launch_bounds__(256, 3) void fused_G_tc(const float* __restrict__ XW1,
                                                     const bf16* __restrict__ dwh,
                                                     const bf16* __restrict__ dwl,
                                                     const bf16* __restrict__ chh,
                                                     const bf16* __restrict__ chl,
                                                     const float* __restrict__ b1,
                                                     bf16* __restrict__ gh,
                                                     bf16* __restrict__ gl)
{
    extern __shared__ __align__(16) char sm[];
    bf16*  sXh = (bf16*)(sm + FG_SXH);
    bf16*  sXl = (bf16*)(sm + FG_SXL);
    bf16*  sHh = (bf16*)(sm + FG_SHH);
    bf16*  sHl = (bf16*)(sm + FG_SHL);
    float* sb  = (float*)(sm + FG_SB);

    const int bx = blockIdx.x;
    const int half = bx & 1;
    const int n  = (bx >> 1) & (Ne - 1);
    const int b  = bx >> 5;
    const int h0g = half * 344;
    const int t = threadIdx.x;
    const int w = t >> 5, lane = t & 31;
    const int gid = lane >> 2, qid = lane & 3;
    const long long mstep = (long long)NHt;

    // ---- local bias
    for (int hl = t; hl < HLEN; hl += 256) {
        const int h = h0g + hl;
        sb[hl] = (hl < 344 && h < Hh) ? b1[n * Hh + h] : 0.f;
    }

    // ---- stage local XW1 slice -> sX[hl][m] bf16 hi/lo
    #pragma unroll 1
    for (int mm = 0; mm < Mt; ++mm) {
        const long long rb = ((long long)(b * Mt + mm) * Ne + n) * Hh;
        for (int hl = t; hl < HLEN; hl += 256) {
            const int h = h0g + hl;
            const float v = (hl < 344 && h < Hh) ? XW1[rb + h] : 0.f;
            bf16 hi, lo; split2(v, hi, lo);
            sXh[hl * XH_STR + mm] = hi;
            sXl[hl * XH_STR + mm] = lo;
        }
    }
    __syncthreads();

    float acc[6][4];
    #pragma unroll
    for (int i = 0; i < 6; ++i)
        #pragma unroll
        for (int e = 0; e < 4; ++e) acc[i][e] = 0.f;

    const int NCH = NTILE;  // 43 p-chunks (43*16 = 688 = padded extent)
    const long long dwbn = (long long)((b * Ne + n)) * HhP * Mt;
    const int moff = qid * 2;

    for (int c = 0; c < NCH; ++c) {
        const int P0 = c * 16;
        // ---- Dw A-fragments: direct loads from pre-split transposed Dwt[p][m]
        uint32_t dah[4], dal[4];
        {
            const long long r0 = dwbn + (long long)(P0 + gid) * Mt + moff;
            const long long r8 = dwbn + (long long)(P0 + gid + 8) * Mt + moff;
            dah[0] = *(const uint32_t*)(dwh + r0);
            dah[1] = *(const uint32_t*)(dwh + r8);
            dah[2] = *(const uint32_t*)(dwh + r0 + 8);
            dah[3] = *(const uint32_t*)(dwh + r8 + 8);
            dal[0] = *(const uint32_t*)(dwl + r0);
            dal[1] = *(const uint32_t*)(dwl + r8);
            dal[2] = *(const uint32_t*)(dwl + r0 + 8);
            dal[3] = *(const uint32_t*)(dwl + r8 + 8);
        }
        // ---- Cw A-fragments: direct loads from pre-split bf16
        uint32_t cah[4], cal[4];
        {
            const long long c0r = ((long long)(b * Mt + gid) * Ne + n) * Hh;
            const long long c8r = c0r + 8 * mstep;
            const int k0 = P0 + qid * 2;
            const int k8 = k0 + 8;
            if (k0 + 1 < Hh) {
                cah[0] = *(const uint32_t*)(chh + c0r + k0);
                cal[0] = *(const uint32_t*)(chl + c0r + k0);
                cah[1] = *(const uint32_t*)(chh + c8r + k0);
                cal[1] = *(const uint32_t*)(chl + c8r + k0);
            } else { cah[0] = cal[0] = cah[1] = cal[1] = 0; }
            if (k8 + 1 < Hh) {
                cah[2] = *(const uint32_t*)(chh + c0r + k8);
                cal[2] = *(const uint32_t*)(chl + c0r + k8);
                cah[3] = *(const uint32_t*)(chh + c8r + k8);
                cal[3] = *(const uint32_t*)(chl + c8r + k8);
            } else if (k8 < Hh) {
                uint32_t vh = (uint32_t)*(const uint16_t*)(chh + c0r + k8);
                uint32_t vl = (uint32_t)*(const uint16_t*)(chl + c0r + k8);
                cah[2] = vh; cal[2] = vl;
                vh = (uint32_t)*(const uint16_t*)(chh + c8r + k8);
                vl = (uint32_t)*(const uint16_t*)(chl + c8r + k8);
                cah[3] = vh; cal[3] = vl;
            } else { cah[2] = cal[2] = cah[3] = cal[3] = 0; }
        }

        // ---- stage 1: H = Dw^T @ XW1, +bias, relu -> sH[hl][p]
        #pragma unroll
        for (int ti = 0; ti < 6; ++ti) {
            const int twl = w + ti * 8;
            if (twl >= NTILE) break;
            const int hrow = twl * 8 + gid;
            const uint32_t xh0 = *(const uint32_t*)(sXh + hrow * XH_STR + qid * 2);
            const uint32_t xh1 = *(const uint32_t*)(sXh + hrow * XH_STR + qid * 2 + 8);
            const uint32_t xl0 = *(const uint32_t*)(sXl + hrow * XH_STR + qid * 2);
            const uint32_t xl1 = *(const uint32_t*)(sXl + hrow * XH_STR + qid * 2 + 8);
            float cf[4] = {0.f, 0.f, 0.f, 0.f};
            mma_bf16(cf, dah[0], dah[1], dah[2], dah[3], xh0, xh1);
            mma_bf16(cf, dah[0], dah[1], dah[2], dah[3], xl0, xl1);
            mma_bf16(cf, dal[0], dal[1], dal[2], dal[3], xh0, xh1);
            const int ha = twl * 8 + qid * 2, hb = ha + 1;
            const float ba = sb[ha], bb = sb[hb];
            const float v00 = fmaxf(cf[0] + ba, 0.f);
            const float v01 = fmaxf(cf[1] + bb, 0.f);
            const float v10 = fmaxf(cf[2] + ba, 0.f);
            const float v11 = fmaxf(cf[3] + bb, 0.f);
            bf16 hi, lo;
            split2(v00, hi, lo); sHh[ha * XH_STR + gid]     = hi; sHl[ha * XH_STR + gid]     = lo;
            split2(v01, hi, lo); sHh[hb * XH_STR + gid]     = hi; sHl[hb * XH_STR + gid]     = lo;
            split2(v10, hi, lo); sHh[ha * XH_STR + gid + 8] = hi; sHl[ha * XH_STR + gid + 8] = lo;
            split2(v11, hi, lo); sHh[hb * XH_STR + gid + 8] = hi; sHl[hb * XH_STR + gid + 8] = lo;
        }
        __syncwarp();

        // ---- stage 2: G += Cw_chunk @ H_chunk
        #pragma unroll
        for (int ti = 0; ti < 6; ++ti) {
            const int twl = w + ti * 8;
            if (twl >= NTILE) break;
            const int hrow = twl * 8 + gid;
            const uint32_t hh0 = *(const uint32_t*)(sHh + hrow * XH_STR + qid * 2);
            const uint32_t hh1 = *(const uint32_t*)(sHh + hrow * XH_STR + qid * 2 + 8);
            const uint32_t hl0 = *(const uint32_t*)(sHl + hrow * XH_STR + qid * 2);
            const uint32_t hl1 = *(const uint32_t*)(sHl + hrow * XH_STR + qid * 2 + 8);
            mma_bf16(acc[ti], cah[0], cah[1], cah[2], cah[3], hh0, hh1);
            mma_bf16(acc[ti], cah[0], cah[1], cah[2], cah[3], hl0, hl1);
            mma_bf16(acc[ti], cal[0], cal[1], cal[2], cal[3], hh0, hh1);
        }
        __syncwarp();
    }

    // ---- store G (bf16 hi/lo)
    const long long g0 = ((long long)(b * Mt + gid) * Ne + n) * Hh;
    const long long g8 = g0 + 8 * mstep;
    #pragma unroll
    for (int ti = 0; ti < 6; ++ti) {
        const int twl = w + ti * 8;
        if (twl >= NTILE) break;
        const int ha = h0g + twl * 8 + qid * 2, hb = ha + 1;
        if (ha < Hh) {
            st_split(gh, gl, g0 + ha, acc[ti][0]);
            st_split(gh, gl, g8 + ha, acc[ti][2]);
        }
        if (hb < Hh) {
            st_split(gh, gl, g0 + hb, acc[ti][1]);
            st_split(gh, gl, g8 + hb, acc[ti][3]);
        }
    }
}

// ---------------- ypart_reduce ----------------
__global__ void ypart_reduce(const float* __restrict__ part, const float* __restrict__ b2s,
                             float* __restrict__ Y)
{
    const int i4 = blockIdx.x * blockDim.x + threadIdx.x;
    const int idx = i4 * 4;
    const int col = idx & (OUTD - 1);
    float4 s = *(const float4*)(b2s + col);
    #pragma unroll
    for (int z = 0; z < YSPLIT; ++z) {
        float4 p = *(const float4*)(part + z * (Rows * OUTD) + idx);
        s.x += p.x; s.y += p.y; s.z += p.z; s.w += p.w;
    }
    *(float4*)(Y + idx) = s;
}

// ---------------- output GEMM ----------------
__global__ __launch_bounds__(128) void out_partial(const float* __restrict__ Y,
                                                   const float* __restrict__ Wout,
                                                   float* __restrict__ part)
{
    constexpr int KC = (Mt * Dd) / OSPLIT;
    __shared__ float ys[Bb][KC];
    const int tid = threadIdx.x;
    const int col = tid * 4;
    const int k0  = blockIdx.y * KC;

    for (int idx = tid; idx < Bb * KC; idx += 128) {
        const int bi = idx / KC, kk = idx - bi * KC;
        ys[bi][kk] = Y[bi * (Mt * Dd) + k0 + kk];
    }
    __syncthreads();

    float4 acc[Bb];
    #pragma unroll
    for (int bi = 0; bi < Bb; ++bi) acc[bi] = make_float4(0.f,0.f,0.f,0.f);

    for (int kk = 0; kk < KC; ++kk) {
        const float4 w = *(const float4*)(Wout + (k0 + kk) * OUTD + col);
        #pragma unroll
        for (int bi = 0; bi < Bb; ++bi) {
            const float yv = ys[bi][kk];
            acc[bi].x = fmaf(yv, w.x, acc[bi].x);
            acc[bi].y = fmaf(yv, w.y, acc[bi].y);
            acc[bi].z = fmaf(yv, w.z, acc[bi].z);
            acc[bi].w = fmaf(yv, w.w, acc[bi].w);
        }
    }
    #pragma unroll
    for (int bi = 0; bi < Bb; ++bi)
        *(float4*)(part + (blockIdx.y * Bb + bi) * OUTD + col) = acc[bi];
}

__global__ void out_reduce(const float* __restrict__ part, const float* __restrict__ bout,
                           float* __restrict__ out)
{
    const int i4 = blockIdx.x * blockDim.x + threadIdx.x;
    const int idx = i4 * 4;
    const int col = idx & (OUTD - 1);
    const int bi  = idx >> 9;
    float4 s = *(const float4*)(bout + col);
    #pragma unroll
    for (int z = 0; z < OSPLIT; ++z) {
        float4 p = *(const float4*)(part + (z * Bb + bi) * OUTD + col);
        s.x += p.x; s.y += p.y; s.z += p.z; s.w += p.w;
    }
    *(float4*)(out + idx) = s;
}

// ---------------- launch ----------------
extern "C" void kernel_launch(void* const* d_in, const int* in_sizes, int n_in,
                              void* d_out, int out_size)
{
    const float* x    = (const float*)d_in[0];
    const float* phi  = (const float*)d_in[1];
    const float* W1   = (const float*)d_in[2];
    const float* b1   = (const float*)d_in[3];
    const float* W2   = (const float*)d_in[4];
    const float* b2   = (const float*)d_in[5];
    const float* Wout = (const float*)d_in[6];
    const float* bout = (const float*)d_in[7];
    float* out = (float*)d_out;

    float *p_logits, *p_XW1, *p_Ypart, *p_Y, *p_b2sum, *p_opart;
    bf16 *p_xh, *p_xl, *p_gh, *p_gl, *p_chh, *p_chl, *p_dwh, *p_dwl;
    cudaGetSymbolAddress((void**)&p_logits, g_logits);
    cudaGetSymbolAddress((void**)&p_XW1,    g_XW1);
    cudaGetSymbolAddress((void**)&p_Ypart,  g_Ypart);
    cudaGetSymbolAddress((void**)&p_Y,      g_Y);
    cudaGetSymbolAddress((void**)&p_b2sum,  g_b2sum);
    cudaGetSymbolAddress((void**)&p_opart,  g_opart);
    cudaGetSymbolAddress((void**)&p_xh,   g_xh);
    cudaGetSymbolAddress((void**)&p_xl,   g_xl);
    cudaGetSymbolAddress((void**)&p_gh,   g_gh);
    cudaGetSymbolAddress((void**)&p_gl,   g_gl);
    cudaGetSymbolAddress((void**)&p_chh,  g_chh);
    cudaGetSymbolAddress((void**)&p_chl,  g_chl);
    cudaGetSymbolAddress((void**)&p_dwh,  g_dwh);
    cudaGetSymbolAddress((void**)&p_dwl,  g_dwl);

    cudaFuncSetAttribute(mma_gemm<0>, cudaFuncAttributeMaxDynamicSharedMemorySize, MG_SMEM);
    cudaFuncSetAttribute(mma_gemm<1>, cudaFuncAttributeMaxDynamicSharedMemorySize, MG_SMEM);
    cudaFuncSetAttribute(fused_G_tc,  cudaFuncAttributeMaxDynamicSharedMemorySize, FG_SMEM);

    prep_k<<<CVT_BLOCKS + 2, 256>>>(x, p_xh, p_xl, b2, p_b2sum);

    const dim3 gBig((NHt + 63)/64, Rows/128, 1);             // 171 x 2
    mma_gemm<0><<<gBig, 256, MG_SMEM>>>(p_xh, p_xl, phi, p_logits, NHt, Dd, 1);
    mma_gemm<1><<<gBig, 256, MG_SMEM>>>(p_xh, p_xl, W1,  p_XW1,    NHt, Dd, 1);

    softmax_np<<<Rows, 256>>>(p_logits, p_chh, p_chl);
    dw_split  <<<(Bb*Ne*HhP)/256, 256>>>(p_logits, p_dwh, p_dwl);

    fused_G_tc<<<Bb*Ne*2, 256, FG_SMEM>>>(p_XW1, p_dwh, p_dwl, p_chh, p_chl, b1, p_gh, p_gl);

    const dim3 gY(OUTD/64, Rows/128, YSPLIT);                // 8 x 2 x 16
    mma_gemm<0><<<gY, 256, MG_SMEM>>>(p_gh, p_gl, W2, p_Ypart, OUTD, NHt, YSPLIT);
    ypart_reduce<<<(Rows*OUTD/4)/256, 256>>>(p_Ypart, p_b2sum, p_Y);

    const dim3 gO(1, OSPLIT, 1);
    out_partial<<<gO, 128>>>(p_Y, Wout, p_opart);
    out_reduce <<<(Bb*OUTD/4)/256, 256>>>(p_opart, bout, out);
}

// round 13
// speedup vs baseline: 1.5899x; 1.0548x over previous
#include <cuda_runtime.h>
#include <cuda_bf16.h>
#include <math.h>
#include <stdint.h>

#define Bb   16
#define Mt   16
#define Dd   512
#define Ne   16
#define Hh   682
#define HhP  688          /* padded p extent */
#define NHt  (Ne*Hh)      /* 10912 */
#define Rows (Bb*Mt)      /* 256   */
#define OUTD 512
#define YSPLIT 16
#define OSPLIT 64

typedef unsigned long long ull;
typedef __nv_bfloat16 bf16;

// ---- warp mma: D(16x8 f32) += A(16x16 bf16) * B(16x8 bf16) ----
__device__ __forceinline__ void mma_bf16(float* c, uint32_t a0, uint32_t a1, uint32_t a2, uint32_t a3,
                                         uint32_t b0, uint32_t b1) {
    asm volatile("mma.sync.aligned.m16n8k16.row.col.f32.bf16.bf16.f32 "
        "{%0,%1,%2,%3}, {%4,%5,%6,%7}, {%8,%9}, {%0,%1,%2,%3};"
        : "+f"(c[0]), "+f"(c[1]), "+f"(c[2]), "+f"(c[3])
        : "r"(a0), "r"(a1), "r"(a2), "r"(a3), "r"(b0), "r"(b1));
}

__device__ __forceinline__ void split2(float v, bf16& h, bf16& l) {
    h = __float2bfloat16(v);
    l = __float2bfloat16(v - __bfloat162float(h));
}
__device__ __forceinline__ void st_split(bf16* gh, bf16* gl, long long idx, float v) {
    bf16 h, l; split2(v, h, l);
    gh[idx] = h; gl[idx] = l;
}

// ---------------- scratch ----------------
__device__ float g_logits[Rows*NHt];
__device__ float g_XW1[Rows*NHt];
__device__ float g_Ypart[YSPLIT*Rows*OUTD];
__device__ float g_Y[Rows*OUTD];
__device__ float g_b2sum[OUTD];
__device__ float g_opart[OSPLIT*Bb*OUTD];
__device__ bf16 g_xh[Rows*Dd],  g_xl[Rows*Dd];
__device__ bf16 g_gh[Rows*NHt], g_gl[Rows*NHt];
__device__ bf16 g_chh[Rows*NHt], g_chl[Rows*NHt];
__device__ bf16 g_dwh[Bb*Ne*HhP*Mt], g_dwl[Bb*Ne*HhP*Mt];   // Dw^T pre-split [b][n][p][m]

// ---------------- prep: x split + b2sum ----------------
#define CVT_BLOCKS (Rows*Dd/4/256)      /* 128 */
__global__ void prep_k(const float* __restrict__ src, bf16* __restrict__ hi,
                       bf16* __restrict__ lo, const float* __restrict__ b2,
                       float* __restrict__ b2s)
{
    const int bx = blockIdx.x;
    if (bx < CVT_BLOCKS) {
        const int i = bx * 256 + threadIdx.x;
        const float4 v = ((const float4*)src)[i];
        bf16 h[4], l[4];
        const float vv[4] = {v.x, v.y, v.z, v.w};
        #pragma unroll
        for (int e = 0; e < 4; ++e) split2(vv[e], h[e], l[e]);
        *(ull*)(hi + i * 4) = *(const ull*)h;
        *(ull*)(lo + i * 4) = *(const ull*)l;
    } else {
        const int d = (bx - CVT_BLOCKS) * 256 + threadIdx.x;
        if (d < OUTD) {
            float s = 0.f;
            #pragma unroll
            for (int n = 0; n < Ne; ++n) s += b2[n * OUTD + d];
            b2s[d] = s;
        }
    }
}

// ---------------- combined: softmax_np (blocks 0..255) + dw_split (blocks 256..943) ----------------
__global__ void softdw(const float* __restrict__ L, bf16* __restrict__ chh,
                       bf16* __restrict__ chl, bf16* __restrict__ dwh,
                       bf16* __restrict__ dwl)
{
    __shared__ float s[Ne * 688];
    const int tid = threadIdx.x;

    if (blockIdx.x < Rows) {
        // ======== softmax_np on row bm ========
        const int bm = blockIdx.x;
        const float* Lrow = L + bm * NHt;

        for (int i4 = tid; i4 < NHt / 4; i4 += 256) {
            const float4 v = *(const float4*)(Lrow + i4 * 4);
            const int idx = i4 * 4;
            const int n = idx / Hh;
            const int p = idx - n * Hh;
            float vv[4] = {v.x, v.y, v.z, v.w};
            int nn = n, pp = p;
            #pragma unroll
            for (int e = 0; e < 4; ++e) {
                s[nn * 688 + pp] = vv[e];
                if (++pp >= Hh) { pp = 0; ++nn; }
            }
        }
        __syncthreads();

        for (int p = tid; p < Hh; p += 256) {
            float mx = -3.4e38f;
            #pragma unroll
            for (int n = 0; n < Ne; ++n) mx = fmaxf(mx, s[n * 688 + p]);
            float sum = 0.f;
            #pragma unroll
            for (int n = 0; n < Ne; ++n) {
                const float e = expf(s[n * 688 + p] - mx);
                s[n * 688 + p] = e;
                sum += e;
            }
            const float inv = 1.f / sum;
            #pragma unroll
            for (int n = 0; n < Ne; ++n) s[n * 688 + p] *= inv;
        }
        __syncthreads();

        const int warp = tid >> 5, lane = tid & 31;
        for (int n = warp; n < Ne; n += 8) {
            float mx = -3.4e38f;
            for (int p = lane; p < Hh; p += 32) mx = fmaxf(mx, s[n * 688 + p]);
            #pragma unroll
            for (int o = 16; o; o >>= 1) mx = fmaxf(mx, __shfl_xor_sync(0xffffffffu, mx, o));
            float sum = 0.f;
            for (int p = lane; p < Hh; p += 32) {
                const float e = expf(s[n * 688 + p] - mx);
                s[n * 688 + p] = e;
                sum += e;
            }
            #pragma unroll
            for (int o = 16; o; o >>= 1) sum += __shfl_xor_sync(0xffffffffu, sum, o);
            const float inv = 1.f / sum;
            for (int p = lane; p < Hh; p += 32) {
                bf16 h, l; split2(s[n * 688 + p] * inv, h, l);
                const long long o2 = (long long)bm * NHt + n * Hh + p;
                chh[o2] = h; chl[o2] = l;
            }
        }
    } else {
        // ======== dw_split: one thread per (b,n,p) column ========
        const int col = (blockIdx.x - Rows) * 256 + tid;
        const int p  = col % HhP;
        const int bn = col / HhP;
        const int b  = bn >> 4;
        const int n  = bn & (Ne - 1);

        bf16 h[Mt], l[Mt];
        if (p < Hh) {
            const long long base = ((long long)(b * Mt) * Ne + n) * Hh + p;
            float v[Mt], mx = -3.4e38f;
            #pragma unroll
            for (int m = 0; m < Mt; ++m) { v[m] = L[base + (long long)m * NHt]; mx = fmaxf(mx, v[m]); }
            float sum = 0.f;
            #pragma unroll
            for (int m = 0; m < Mt; ++m) { v[m] = expf(v[m] - mx); sum += v[m]; }
            const float inv = 1.f / sum;
            #pragma unroll
            for (int m = 0; m < Mt; ++m) split2(v[m] * inv, h[m], l[m]);
        } else {
            #pragma unroll
            for (int m = 0; m < Mt; ++m) { h[m] = __float2bfloat16(0.f); l[m] = h[m]; }
        }
        const long long o = (long long)col * Mt;
        #pragma unroll
        for (int q = 0; q < 4; ++q) {
            *(ull*)(dwh + o + q * 4) = *(const ull*)(h + q * 4);
            *(ull*)(dwl + o + q * 4) = *(const ull*)(l + q * 4);
        }
    }
}

// ---------------- mma.sync bf16-split GEMM (R9 proven version) ----------------
#define AS_STR 72
#define BS_STR 74
#define SM_AH 0
#define SM_AL (SM_AH + 128*AS_STR*2)
#define SM_BH (SM_AL + 128*AS_STR*2)
#define SM_BL (SM_BH + 64*BS_STR*2)
#define MG_SMEM (SM_BL + 64*BS_STR*2)    /* 55808 */

template<int MODE>
__global__ __launch_bounds__(256) void mma_gemm(
    const bf16* __restrict__ Ah, const bf16* __restrict__ Al,
    const float* __restrict__ Bm,
    float* __restrict__ C, int Nc, int K, int nsplit)
{
    extern __shared__ __align__(16) char sm[];
    bf16* sAh = (bf16*)(sm + SM_AH);
    bf16* sAl = (bf16*)(sm + SM_AL);
    bf16* sBh = (bf16*)(sm + SM_BH);
    bf16* sBl = (bf16*)(sm + SM_BL);

    const int t = threadIdx.x;
    const int lane = t & 31, warp = t >> 5;
    const int wm = (warp & 3) * 32;
    const int wn = (warp >> 2) * 32;
    const int m0 = blockIdx.y * 128;
    const int j0 = blockIdx.x * 64;
    const int z  = blockIdx.z;
    const int nch = (K + 63) >> 6;
    const int c0 = (int)((long long)nch * z / nsplit);
    const int c1 = (int)((long long)nch * (z + 1) / nsplit);

    float acc[2][4][4];
    #pragma unroll
    for (int i = 0; i < 2; ++i)
        #pragma unroll
        for (int j = 0; j < 4; ++j)
            #pragma unroll
            for (int e = 0; e < 4; ++e) acc[i][j][e] = 0.f;

    const int gid = lane >> 2;
    const int qid = lane & 3;

    int bn[4], bh[4];
    if (MODE == 1) {
        #pragma unroll
        for (int it = 0; it < 4; ++it) {
            const int g = (t + it * 256) & 15;
            const int j = j0 + g * 4;
            int n = j / Hh;
            bn[it] = n;
            bh[it] = j - n * Hh;
        }
    }

    for (int c = c0; c < c1; ++c) {
        const int k0 = c << 6;
        __syncthreads();
        #pragma unroll
        for (int it = 0; it < 8; ++it) {
            const int s = t + it * 256;
            const int kq = s & 15;
            const int row = s >> 4;
            const int gk = k0 + kq * 4;
            const long long ga = (long long)(m0 + row) * K + gk;
            ull vh = 0, vl = 0;
            if (gk + 4 <= K) { vh = *(const ull*)(Ah + ga); vl = *(const ull*)(Al + ga); }
            *(ull*)(sAh + row * AS_STR + kq * 4) = vh;
            *(ull*)(sAl + row * AS_STR + kq * 4) = vl;
        }
        #pragma unroll
        for (int it = 0; it < 4; ++it) {
            const int s = t + it * 256;
            const int g = s & 15;
            const int k = s >> 4;
            const int gj = j0 + g * 4;
            const int gk = k0 + k;
            float vv[4] = {0.f, 0.f, 0.f, 0.f};
            if (MODE == 0) {
                if (gj + 4 <= Nc && gk < K) {
                    const float4 v = *(const float4*)(Bm + (long long)gk * Nc + gj);
                    vv[0] = v.x; vv[1] = v.y; vv[2] = v.z; vv[3] = v.w;
                }
            } else {
                if (gk < K) {
                    int n = bn[it], h = bh[it];
                    #pragma unroll
                    for (int e = 0; e < 4; ++e) {
                        if (gj + e < Nc) vv[e] = Bm[((long long)n * K + gk) * Hh + h];
                        if (++h >= Hh) { h = 0; ++n; }
                    }
                }
            }
            #pragma unroll
            for (int e = 0; e < 4; ++e) {
                bf16 h, l; split2(vv[e], h, l);
                sBh[(g * 4 + e) * BS_STR + k] = h;
                sBl[(g * 4 + e) * BS_STR + k] = l;
            }
        }
        __syncthreads();

        #pragma unroll
        for (int ks = 0; ks < 4; ++ks) {
            const int kcol = ks * 16 + qid * 2;
            uint32_t ah[2][4], al[2][4];
            #pragma unroll
            for (int mi = 0; mi < 2; ++mi) {
                const int r = wm + mi * 16 + gid;
                ah[mi][0] = *(const uint32_t*)(sAh + r * AS_STR + kcol);
                ah[mi][1] = *(const uint32_t*)(sAh + (r + 8) * AS_STR + kcol);
                ah[mi][2] = *(const uint32_t*)(sAh + r * AS_STR + kcol + 8);
                ah[mi][3] = *(const uint32_t*)(sAh + (r + 8) * AS_STR + kcol + 8);
                al[mi][0] = *(const uint32_t*)(sAl + r * AS_STR + kcol);
                al[mi][1] = *(const uint32_t*)(sAl + (r + 8) * AS_STR + kcol);
                al[mi][2] = *(const uint32_t*)(sAl + r * AS_STR + kcol + 8);
                al[mi][3] = *(const uint32_t*)(sAl + (r + 8) * AS_STR + kcol + 8);
            }
            uint32_t bhf[4][2], blf[4][2];
            #pragma unroll
            for (int ni = 0; ni < 4; ++ni) {
                const int n = wn + ni * 8 + gid;
                bhf[ni][0] = *(const uint32_t*)(sBh + n * BS_STR + kcol);
                bhf[ni][1] = *(const uint32_t*)(sBh + n * BS_STR + kcol + 8);
                blf[ni][0] = *(const uint32_t*)(sBl + n * BS_STR + kcol);
                blf[ni][1] = *(const uint32_t*)(sBl + n * BS_STR + kcol + 8);
            }
            #pragma unroll
            for (int mi = 0; mi < 2; ++mi)
                #pragma unroll
                for (int ni = 0; ni < 4; ++ni) {
                    mma_bf16(acc[mi][ni], ah[mi][0], ah[mi][1], ah[mi][2], ah[mi][3],
                             bhf[ni][0], bhf[ni][1]);
                    mma_bf16(acc[mi][ni], ah[mi][0], ah[mi][1], ah[mi][2], ah[mi][3],
                             blf[ni][0], blf[ni][1]);
                    mma_bf16(acc[mi][ni], al[mi][0], al[mi][1], al[mi][2], al[mi][3],
                             bhf[ni][0], bhf[ni][1]);
                }
        }
    }

    float* Cz = C + (long long)z * Rows * Nc;
    #pragma unroll
    for (int mi = 0; mi < 2; ++mi) {
        const int r0 = m0 + wm + mi * 16 + gid;
        #pragma unroll
        for (int ni = 0; ni < 4; ++ni) {
            const int cn = j0 + wn + ni * 8 + qid * 2;
            if (cn < Nc) {
                float2 lo2 = make_float2(acc[mi][ni][0], acc[mi][ni][1]);
                float2 hi2 = make_float2(acc[mi][ni][2], acc[mi][ni][3]);
                *(float2*)(Cz + (long long)r0 * Nc + cn)       = lo2;
                *(float2*)(Cz + (long long)(r0 + 8) * Nc + cn) = hi2;
            }
        }
    }
}

// ---------------- TENSOR fused: full-h per block, pre-split Dw/Cw, prefetch ----------------
#define XH_STR 18
#define FG_SXH 0
#define FG_SXL (FG_SXH + HhP*XH_STR*2)
#define FG_SHH (FG_SXL + HhP*XH_STR*2)
#define FG_SHL (FG_SHH + HhP*XH_STR*2)
#define FG_SB   (FG_SHL + HhP*XH_STR*2)
#define FG_SMEM (FG_SB + HhP*4)          /* 101824 */
#define NTILE 86

__global__ __launch_bounds__(256, 2) void fused_G_tc(const float* __restrict__ XW1,
                                                     const bf16* __restrict__ dwh,
                                                     const bf16* __restrict__ dwl,
                                                     const bf16* __restrict__ chh,
                                                     const bf16* __restrict__ chl,
                                                     const float* __restrict__ b1,
                                                     bf16* __restrict__ gh,
                                                     bf16* __restrict__ gl)
{
    extern __shared__ __align__(16) char sm[];
    bf16*  sXh = (bf16*)(sm + FG_SXH);
    bf16*  sXl = (bf16*)(sm + FG_SXL);
    bf16*  sHh = (bf16*)(sm + FG_SHH);
    bf16*  sHl = (bf16*)(sm + FG_SHL);
    float* sb  = (float*)(sm + FG_SB);

    const int bx = blockIdx.x;
    const int n  = bx & (Ne - 1);
    const int b  = bx >> 4;
    const int t = threadIdx.x;
    const int w = t >> 5, lane = t & 31;
    const int gid = lane >> 2, qid = lane & 3;
    const long long mstep = (long long)NHt;

    for (int h = t; h < HhP; h += 256)
        sb[h] = (h < Hh) ? b1[n * Hh + h] : 0.f;

    #pragma unroll 1
    for (int mm = 0; mm < Mt; ++mm) {
        const long long rb = ((long long)(b * Mt + mm) * Ne + n) * Hh;
        for (int h = t; h < HhP; h += 256) {
            const float v = (h < Hh) ? XW1[rb + h] : 0.f;
            bf16 hi, lo; split2(v, hi, lo);
            sXh[h * XH_STR + mm] = hi;
            sXl[h * XH_STR + mm] = lo;
        }
    }
    __syncthreads();

    float acc[11][4];
    #pragma unroll
    for (int i = 0; i < 11; ++i)
        #pragma unroll
        for (int e = 0; e < 4; ++e) acc[i][e] = 0.f;

    const int NCH = 43;
    const long long dwbn = (long long)(b * Ne + n) * HhP * Mt;
    const int moff = qid * 2;
    const long long c0r = ((long long)(b * Mt + gid) * Ne + n) * Hh;
    const long long c8r = c0r + 8 * mstep;

    // ---- fragment load helpers (by value of chunk index) ----
    uint32_t dah[4], dal[4], cah[4], cal[4];
    {
        const int P0 = 0;
        const long long r0 = dwbn + (long long)(P0 + gid) * Mt + moff;
        const long long r8 = r0 + 8 * Mt;
        dah[0] = *(const uint32_t*)(dwh + r0);
        dah[1] = *(const uint32_t*)(dwh + r8);
        dah[2] = *(const uint32_t*)(dwh + r0 + 8);
        dah[3] = *(const uint32_t*)(dwh + r8 + 8);
        dal[0] = *(const uint32_t*)(dwl + r0);
        dal[1] = *(const uint32_t*)(dwl + r8);
        dal[2] = *(const uint32_t*)(dwl + r0 + 8);
        dal[3] = *(const uint32_t*)(dwl + r8 + 8);
        const int k0 = P0 + qid * 2, k8 = k0 + 8;
        cah[0] = *(const uint32_t*)(chh + c0r + k0);
        cal[0] = *(const uint32_t*)(chl + c0r + k0);
        cah[1] = *(const uint32_t*)(chh + c8r + k0);
        cal[1] = *(const uint32_t*)(chl + c8r + k0);
        cah[2] = *(const uint32_t*)(chh + c0r + k8);
        cal[2] = *(const uint32_t*)(chl + c0r + k8);
        cah[3] = *(const uint32_t*)(chh + c8r + k8);
        cal[3] = *(const uint32_t*)(chl + c8r + k8);
    }

    for (int c = 0; c < NCH; ++c) {
        // ---- prefetch next chunk's fragments
        uint32_t ndah[4], ndal[4], ncah[4], ncal[4];
        if (c + 1 < NCH) {
            const int P0 = (c + 1) * 16;
            const long long r0 = dwbn + (long long)(P0 + gid) * Mt + moff;
            const long long r8 = r0 + 8 * Mt;
            ndah[0] = *(const uint32_t*)(dwh + r0);
            ndah[1] = *(const uint32_t*)(dwh + r8);
            ndah[2] = *(const uint32_t*)(dwh + r0 + 8);
            ndah[3] = *(const uint32_t*)(dwh + r8 + 8);
            ndal[0] = *(const uint32_t*)(dwl + r0);
            ndal[1] = *(const uint32_t*)(dwl + r8);
            ndal[2] = *(const uint32_t*)(dwl + r0 + 8);
            ndal[3] = *(const uint32_t*)(dwl + r8 + 8);
            const int k0 = P0 + qid * 2, k8 = k0 + 8;
            if (k0 + 1 < Hh) {
                ncah[0] = *(const uint32_t*)(chh + c0r + k0);
                ncal[0] = *(const uint32_t*)(chl + c0r + k0);
                ncah[1] = *(const uint32_t*)(chh + c8r + k0);
                ncal[1] = *(const uint32_t*)(chl + c8r + k0);
            } else { ncah[0] = ncal[0] = ncah[1] = ncal[1] = 0; }
            if (k8 + 1 < Hh) {
                ncah[2] = *(const uint32_t*)(chh + c0r + k8);
                ncal[2] = *(const uint32_t*)(chl + c0r + k8);
                ncah[3] = *(const uint32_t*)(chh + c8r + k8);
                ncal[3] = *(const uint32_t*)(chl + c8r + k8);
            } else { ncah[2] = ncal[2] = ncah[3] = ncal[3] = 0; }
        } else {
            #pragma unroll
            for (int i = 0; i < 4; ++i) { ndah[i] = ndal[i] = ncah[i] = ncal[i] = 0; }
        }

        // ---- stage 1: H = Dw^T @ XW1, +bias, relu -> sH[h][p]
        #pragma unroll
        for (int ti = 0; ti < 11; ++ti) {
            const int tw = w + ti * 8;
            if (tw >= NTILE) break;
            const int hrow = tw * 8 + gid;
            const uint32_t xh0 = *(const uint32_t*)(sXh + hrow * XH_STR + qid * 2);
            const uint32_t xh1 = *(const uint32_t*)(sXh + hrow * XH_STR + qid * 2 + 8);
            const uint32_t xl0 = *(const uint32_t*)(sXl + hrow * XH_STR + qid * 2);
            const uint32_t xl1 = *(const uint32_t*)(sXl + hrow * XH_STR + qid * 2 + 8);
            float cf[4] = {0.f, 0.f, 0.f, 0.f};
            mma_bf16(cf, dah[0], dah[1], dah[2], dah[3], xh0, xh1);
            mma_bf16(cf, dah[0], dah[1], dah[2], dah[3], xl0, xl1);
            mma_bf16(cf, dal[0], dal[1], dal[2], dal[3], xh0, xh1);
            const int ha = tw * 8 + qid * 2, hb = ha + 1;
            const float ba = sb[ha], bb = sb[hb];
            const float v00 = fmaxf(cf[0] + ba, 0.f);
            const float v01 = fmaxf(cf[1] + bb, 0.f);
            const float v10 = fmaxf(cf[2] + ba, 0.f);
            const float v11 = fmaxf(cf[3] + bb, 0.f);
            bf16 hi, lo;
            split2(v00, hi, lo); sHh[ha * XH_STR + gid]     = hi; sHl[ha * XH_STR + gid]     = lo;
            split2(v01, hi, lo); sHh[hb * XH_STR + gid]     = hi; sHl[hb * XH_STR + gid]     = lo;
            split2(v10, hi, lo); sHh[ha * XH_STR + gid + 8] = hi; sHl[ha * XH_STR + gid + 8] = lo;
            split2(v11, hi, lo); sHh[hb * XH_STR + gid + 8] = hi; sHl[hb * XH_STR + gid + 8] = lo;
        }
        __syncwarp();

        // ---- stage 2: G += Cw_chunk @ H_chunk
        #pragma unroll
        for (int ti = 0; ti < 11; ++ti) {
            const int tw = w + ti * 8;
            if (tw >= NTILE) break;
            const int hrow = tw * 8 + gid;
            const uint32_t hh0 = *(const uint32_t*)(sHh + hrow * XH_STR + qid * 2);
            const uint32_t hh1 = *(const uint32_t*)(sHh + hrow * XH_STR + qid * 2 + 8);
            const uint32_t hl0 = *(const uint32_t*)(sHl + hrow * XH_STR + qid * 2);
            const uint32_t hl1 = *(const uint32_t*)(sHl + hrow * XH_STR + qid * 2 + 8);
            mma_bf16(acc[ti], cah[0], cah[1], cah[2], cah[3], hh0, hh1);
            mma_bf16(acc[ti], cah[0], cah[1], cah[2], cah[3], hl0, hl1);
            mma_bf16(acc[ti], cal[0], cal[1], cal[2], cal[3], hh0, hh1);
        }
        __syncwarp();

        #pragma unroll
        for (int i = 0; i < 4; ++i) {
            dah[i] = ndah[i]; dal[i] = ndal[i];
            cah[i] = ncah[i]; cal[i] = ncal[i];
        }
    }

    // ---- store G (bf16 hi/lo)
    const long long g0 = ((long long)(b * Mt + gid) * Ne + n) * Hh;
    const long long g8 = g0 + 8 * mstep;
    #pragma unroll
    for (int ti = 0; ti < 11; ++ti) {
        const int tw = w + ti * 8;
        if (tw >= NTILE) break;
        const int ha = tw * 8 + qid * 2, hb = ha + 1;
        if (ha < Hh) {
            st_split(gh, gl, g0 + ha, acc[ti][0]);
            st_split(gh, gl, g8 + ha, acc[ti][2]);
        }
        if (hb < Hh) {
            st_split(gh, gl, g0 + hb, acc[ti][1]);
            st_split(gh, gl, g8 + hb, acc[ti][3]);
        }
    }
}

// ---------------- ypart_reduce ----------------
__global__ void ypart_reduce(const float* __restrict__ part, const float* __restrict__ b2s,
                             float* __restrict__ Y)
{
    const int i4 = blockIdx.x * blockDim.x + threadIdx.x;
    const int idx = i4 * 4;
    const int col = idx & (OUTD - 1);
    float4 s = *(const float4*)(b2s + col);
    #pragma unroll
    for (int z = 0; z < YSPLIT; ++z) {
        float4 p = *(const float4*)(part + z * (Rows * OUTD) + idx);
        s.x += p.x; s.y += p.y; s.z += p.z; s.w += p.w;
    }
    *(float4*)(Y + idx) = s;
}

// ---------------- output GEMM ----------------
__global__ __launch_bounds__(128) void out_partial(const float* __restrict__ Y,
                                                   const float* __restrict__ Wout,
                                                   float* __restrict__ part)
{
    constexpr int KC = (Mt * Dd) / OSPLIT;
    __shared__ float ys[Bb][KC];
    const int tid = threadIdx.x;
    const int col = tid * 4;
    const int k0  = blockIdx.y * KC;

    for (int idx = tid; idx < Bb * KC; idx += 128) {
        const int bi = idx / KC, kk = idx - bi * KC;
        ys[bi][kk] = Y[bi * (Mt * Dd) + k0 + kk];
    }
    __syncthreads();

    float4 acc[Bb];
    #pragma unroll
    for (int bi = 0; bi < Bb; ++bi) acc[bi] = make_float4(0.f,0.f,0.f,0.f);

    for (int kk = 0; kk < KC; ++kk) {
        const float4 w = *(const float4*)(Wout + (k0 + kk) * OUTD + col);
        #pragma unroll
        for (int bi = 0; bi < Bb; ++bi) {
            const float yv = ys[bi][kk];
            acc[bi].x = fmaf(yv, w.x, acc[bi].x);
            acc[bi].y = fmaf(yv, w.y, acc[bi].y);
            acc[bi].z = fmaf(yv, w.z, acc[bi].z);
            acc[bi].w = fmaf(yv, w.w, acc[bi].w);
        }
    }
    #pragma unroll
    for (int bi = 0; bi < Bb; ++bi)
        *(float4*)(part + (blockIdx.y * Bb + bi) * OUTD + col) = acc[bi];
}

__global__ void out_reduce(const float* __restrict__ part, const float* __restrict__ bout,
                           float* __restrict__ out)
{
    const int i4 = blockIdx.x * blockDim.x + threadIdx.x;
    const int idx = i4 * 4;
    const int col = idx & (OUTD - 1);
    const int bi  = idx >> 9;
    float4 s = *(const float4*)(bout + col);
    #pragma unroll
    for (int z = 0; z < OSPLIT; ++z) {
        float4 p = *(const float4*)(part + (z * Bb + bi) * OUTD + col);
        s.x += p.x; s.y += p.y; s.z += p.z; s.w += p.w;
    }
    *(float4*)(out + idx) = s;
}

// ---------------- launch ----------------
extern "C" void kernel_launch(void* const* d_in, const int* in_sizes, int n_in,
                              void* d_out, int out_size)
{
    const float* x    = (const float*)d_in[0];
    const float* phi  = (const float*)d_in[1];
    const float* W1   = (const float*)d_in[2];
    const float* b1   = (const float*)d_in[3];
    const float* W2   = (const float*)d_in[4];
    const float* b2   = (const float*)d_in[5];
    const float* Wout = (const float*)d_in[6];
    const float* bout = (const float*)d_in[7];
    float* out = (float*)d_out;

    float *p_logits, *p_XW1, *p_Ypart, *p_Y, *p_b2sum, *p_opart;
    bf16 *p_xh, *p_xl, *p_gh, *p_gl, *p_chh, *p_chl, *p_dwh, *p_dwl;
    cudaGetSymbolAddress((void**)&p_logits, g_logits);
    cudaGetSymbolAddress((void**)&p_XW1,    g_XW1);
    cudaGetSymbolAddress((void**)&p_Ypart,  g_Ypart);
    cudaGetSymbolAddress((void**)&p_Y,      g_Y);
    cudaGetSymbolAddress((void**)&p_b2sum,  g_b2sum);
    cudaGetSymbolAddress((void**)&p_opart,  g_opart);
    cudaGetSymbolAddress((void**)&p_xh,   g_xh);
    cudaGetSymbolAddress((void**)&p_xl,   g_xl);
    cudaGetSymbolAddress((void**)&p_gh,   g_gh);
    cudaGetSymbolAddress((void**)&p_gl,   g_gl);
    cudaGetSymbolAddress((void**)&p_chh,  g_chh);
    cudaGetSymbolAddress((void**)&p_chl,  g_chl);
    cudaGetSymbolAddress((void**)&p_dwh,  g_dwh);
    cudaGetSymbolAddress((void**)&p_dwl,  g_dwl);

    cudaFuncSetAttribute(mma_gemm<0>, cudaFuncAttributeMaxDynamicSharedMemorySize, MG_SMEM);
    cudaFuncSetAttribute(mma_gemm<1>, cudaFuncAttributeMaxDynamicSharedMemorySize, MG_SMEM);
    cudaFuncSetAttribute(fused_G_tc,  cudaFuncAttributeMaxDynamicSharedMemorySize, FG_SMEM);

    const dim3 gBig((NHt + 63)/64, Rows/128, 1);             // 171 x 2

    prep_k<<<CVT_BLOCKS + 2, 256>>>(x, p_xh, p_xl, b2, p_b2sum);                 // 1
    mma_gemm<0><<<gBig, 256, MG_SMEM>>>(p_xh, p_xl, phi, p_logits, NHt, Dd, 1);  // 2
    softdw<<<Rows + (Bb*Ne*HhP)/256, 256>>>(p_logits, p_chh, p_chl, p_dwh, p_dwl); // 3
    mma_gemm<1><<<gBig, 256, MG_SMEM>>>(p_xh, p_xl, W1, p_XW1, NHt, Dd, 1);      // 4 (profiled)

    fused_G_tc<<<Bb*Ne, 256, FG_SMEM>>>(p_XW1, p_dwh, p_dwl, p_chh, p_chl, b1, p_gh, p_gl); // 5

    const dim3 gY(OUTD/64, Rows/128, YSPLIT);                // 8 x 2 x 16
    mma_gemm<0><<<gY, 256, MG_SMEM>>>(p_gh, p_gl, W2, p_Ypart, OUTD, NHt, YSPLIT); // 6
    ypart_reduce<<<(Rows*OUTD/4)/256, 256>>>(p_Ypart, p_b2sum, p_Y);             // 7

    const dim3 gO(1, OSPLIT, 1);
    out_partial<<<gO, 128>>>(p_Y, Wout, p_opart);                                 // 8
    out_reduce <<<(Bb*OUTD/4)/256, 256>>>(p_opart, bout, out);                    // 9
}

// round 14
// speedup vs baseline: 1.6467x; 1.0357x over previous
#include <cuda_runtime.h>
#include <cuda_bf16.h>
#include <math.h>
#include <stdint.h>

#define Bb   16
#define Mt   16
#define Dd   512
#define Ne   16
#define Hh   682
#define HhP  688          /* padded p extent */
#define NHt  (Ne*Hh)      /* 10912 */
#define Rows (Bb*Mt)      /* 256   */
#define OUTD 512
#define YSPLIT 16
#define OSPLIT 64

typedef unsigned long long ull;
typedef __nv_bfloat16 bf16;

// ---- warp mma: D(16x8 f32) += A(16x16 bf16) * B(16x8 bf16) ----
__device__ __forceinline__ void mma_bf16(float* c, uint32_t a0, uint32_t a1, uint32_t a2, uint32_t a3,
                                         uint32_t b0, uint32_t b1) {
    asm volatile("mma.sync.aligned.m16n8k16.row.col.f32.bf16.bf16.f32 "
        "{%0,%1,%2,%3}, {%4,%5,%6,%7}, {%8,%9}, {%0,%1,%2,%3};"
        : "+f"(c[0]), "+f"(c[1]), "+f"(c[2]), "+f"(c[3])
        : "r"(a0), "r"(a1), "r"(a2), "r"(a3), "r"(b0), "r"(b1));
}

__device__ __forceinline__ void split2(float v, bf16& h, bf16& l) {
    h = __float2bfloat16(v);
    l = __float2bfloat16(v - __bfloat162float(h));
}
__device__ __forceinline__ void st_split(bf16* gh, bf16* gl, long long idx, float v) {
    bf16 h, l; split2(v, h, l);
    gh[idx] = h; gl[idx] = l;
}

// ---------------- scratch ----------------
__device__ float g_logits[Rows*NHt];
__device__ float g_XW1[Rows*NHt];
__device__ float g_Ypart[YSPLIT*Rows*OUTD];
__device__ float g_Y[Rows*OUTD];
__device__ float g_b2sum[OUTD];
__device__ float g_opart[OSPLIT*Bb*OUTD];
__device__ bf16 g_xh[Rows*Dd],  g_xl[Rows*Dd];
__device__ bf16 g_gh[Rows*NHt], g_gl[Rows*NHt];
__device__ bf16 g_chh[Rows*NHt], g_chl[Rows*NHt];
__device__ bf16 g_dwh[Bb*Ne*HhP*Mt], g_dwl[Bb*Ne*HhP*Mt];   // Dw^T pre-split [b][n][p][m]

// ---------------- prep: x split + b2sum ----------------
#define CVT_BLOCKS (Rows*Dd/4/256)      /* 128 */
__global__ void prep_k(const float* __restrict__ src, bf16* __restrict__ hi,
                       bf16* __restrict__ lo, const float* __restrict__ b2,
                       float* __restrict__ b2s)
{
    const int bx = blockIdx.x;
    if (bx < CVT_BLOCKS) {
        const int i = bx * 256 + threadIdx.x;
        const float4 v = ((const float4*)src)[i];
        bf16 h[4], l[4];
        const float vv[4] = {v.x, v.y, v.z, v.w};
        #pragma unroll
        for (int e = 0; e < 4; ++e) split2(vv[e], h[e], l[e]);
        *(ull*)(hi + i * 4) = *(const ull*)h;
        *(ull*)(lo + i * 4) = *(const ull*)l;
    } else {
        const int d = (bx - CVT_BLOCKS) * 256 + threadIdx.x;
        if (d < OUTD) {
            float s = 0.f;
            #pragma unroll
            for (int n = 0; n < Ne; ++n) s += b2[n * OUTD + d];
            b2s[d] = s;
        }
    }
}

// ---------------- combined: softmax_np (blocks 0..255) + dw_split (blocks 256..943) ----------------
__global__ void softdw(const float* __restrict__ L, bf16* __restrict__ chh,
                       bf16* __restrict__ chl, bf16* __restrict__ dwh,
                       bf16* __restrict__ dwl)
{
    __shared__ float s[Ne * 688];
    const int tid = threadIdx.x;

    if (blockIdx.x < Rows) {
        const int bm = blockIdx.x;
        const float* Lrow = L + bm * NHt;

        for (int i4 = tid; i4 < NHt / 4; i4 += 256) {
            const float4 v = *(const float4*)(Lrow + i4 * 4);
            const int idx = i4 * 4;
            const int n = idx / Hh;
            const int p = idx - n * Hh;
            float vv[4] = {v.x, v.y, v.z, v.w};
            int nn = n, pp = p;
            #pragma unroll
            for (int e = 0; e < 4; ++e) {
                s[nn * 688 + pp] = vv[e];
                if (++pp >= Hh) { pp = 0; ++nn; }
            }
        }
        __syncthreads();

        for (int p = tid; p < Hh; p += 256) {
            float mx = -3.4e38f;
            #pragma unroll
            for (int n = 0; n < Ne; ++n) mx = fmaxf(mx, s[n * 688 + p]);
            float sum = 0.f;
            #pragma unroll
            for (int n = 0; n < Ne; ++n) {
                const float e = expf(s[n * 688 + p] - mx);
                s[n * 688 + p] = e;
                sum += e;
            }
            const float inv = 1.f / sum;
            #pragma unroll
            for (int n = 0; n < Ne; ++n) s[n * 688 + p] *= inv;
        }
        __syncthreads();

        const int warp = tid >> 5, lane = tid & 31;
        for (int n = warp; n < Ne; n += 8) {
            float mx = -3.4e38f;
            for (int p = lane; p < Hh; p += 32) mx = fmaxf(mx, s[n * 688 + p]);
            #pragma unroll
            for (int o = 16; o; o >>= 1) mx = fmaxf(mx, __shfl_xor_sync(0xffffffffu, mx, o));
            float sum = 0.f;
            for (int p = lane; p < Hh; p += 32) {
                const float e = expf(s[n * 688 + p] - mx);
                s[n * 688 + p] = e;
                sum += e;
            }
            #pragma unroll
            for (int o = 16; o; o >>= 1) sum += __shfl_xor_sync(0xffffffffu, sum, o);
            const float inv = 1.f / sum;
            for (int p = lane; p < Hh; p += 32) {
                bf16 h, l; split2(s[n * 688 + p] * inv, h, l);
                const long long o2 = (long long)bm * NHt + n * Hh + p;
                chh[o2] = h; chl[o2] = l;
            }
        }
    } else {
        const int col = (blockIdx.x - Rows) * 256 + tid;
        const int p  = col % HhP;
        const int bn = col / HhP;
        const int b  = bn >> 4;
        const int n  = bn & (Ne - 1);

        bf16 h[Mt], l[Mt];
        if (p < Hh) {
            const long long base = ((long long)(b * Mt) * Ne + n) * Hh + p;
            float v[Mt], mx = -3.4e38f;
            #pragma unroll
            for (int m = 0; m < Mt; ++m) { v[m] = L[base + (long long)m * NHt]; mx = fmaxf(mx, v[m]); }
            float sum = 0.f;
            #pragma unroll
            for (int m = 0; m < Mt; ++m) { v[m] = expf(v[m] - mx); sum += v[m]; }
            const float inv = 1.f / sum;
            #pragma unroll
            for (int m = 0; m < Mt; ++m) split2(v[m] * inv, h[m], l[m]);
        } else {
            #pragma unroll
            for (int m = 0; m < Mt; ++m) { h[m] = __float2bfloat16(0.f); l[m] = h[m]; }
        }
        const long long o = (long long)col * Mt;
        #pragma unroll
        for (int q = 0; q < 4; ++q) {
            *(ull*)(dwh + o + q * 4) = *(const ull*)(h + q * 4);
            *(ull*)(dwl + o + q * 4) = *(const ull*)(l + q * 4);
        }
    }
}

// ---------------- mma.sync bf16-split GEMM, reg-lean (2 CTAs/SM) ----------------
#define AS_STR 72
#define BS_STR 74
#define SM_AH 0
#define SM_AL (SM_AH + 128*AS_STR*2)
#define SM_BH (SM_AL + 128*AS_STR*2)
#define SM_BL (SM_BH + 64*BS_STR*2)
#define MG_SMEM (SM_BL + 64*BS_STR*2)    /* 55808 */

template<int MODE>
__global__ __launch_bounds__(256, 2) void mma_gemm(
    const bf16* __restrict__ Ah, const bf16* __restrict__ Al,
    const float* __restrict__ Bm,
    float* __restrict__ C, int Nc, int K, int nsplit)
{
    extern __shared__ __align__(16) char sm[];
    bf16* sAh = (bf16*)(sm + SM_AH);
    bf16* sAl = (bf16*)(sm + SM_AL);
    bf16* sBh = (bf16*)(sm + SM_BH);
    bf16* sBl = (bf16*)(sm + SM_BL);

    const int t = threadIdx.x;
    const int lane = t & 31, warp = t >> 5;
    const int wm = (warp & 3) * 32;
    const int wn = (warp >> 2) * 32;
    const int m0 = blockIdx.y * 128;
    const int j0 = blockIdx.x * 64;
    const int z  = blockIdx.z;
    const int nch = (K + 63) >> 6;
    const int c0 = (int)((long long)nch * z / nsplit);
    const int c1 = (int)((long long)nch * (z + 1) / nsplit);

    float acc[2][4][4];
    #pragma unroll
    for (int i = 0; i < 2; ++i)
        #pragma unroll
        for (int j = 0; j < 4; ++j)
            #pragma unroll
            for (int e = 0; e < 4; ++e) acc[i][j][e] = 0.f;

    const int gid = lane >> 2;
    const int qid = lane & 3;

    int bn[4], bh[4];
    if (MODE == 1) {
        #pragma unroll
        for (int it = 0; it < 4; ++it) {
            const int g = (t + it * 256) & 15;
            const int j = j0 + g * 4;
            int n = j / Hh;
            bn[it] = n;
            bh[it] = j - n * Hh;
        }
    }

    for (int c = c0; c < c1; ++c) {
        const int k0 = c << 6;
        __syncthreads();
        #pragma unroll
        for (int it = 0; it < 8; ++it) {
            const int s = t + it * 256;
            const int kq = s & 15;
            const int row = s >> 4;
            const int gk = k0 + kq * 4;
            const long long ga = (long long)(m0 + row) * K + gk;
            ull vh = 0, vl = 0;
            if (gk + 4 <= K) { vh = *(const ull*)(Ah + ga); vl = *(const ull*)(Al + ga); }
            *(ull*)(sAh + row * AS_STR + kq * 4) = vh;
            *(ull*)(sAl + row * AS_STR + kq * 4) = vl;
        }
        #pragma unroll
        for (int it = 0; it < 4; ++it) {
            const int s = t + it * 256;
            const int g = s & 15;
            const int k = s >> 4;
            const int gj = j0 + g * 4;
            const int gk = k0 + k;
            float vv[4] = {0.f, 0.f, 0.f, 0.f};
            if (MODE == 0) {
                if (gj + 4 <= Nc && gk < K) {
                    const float4 v = *(const float4*)(Bm + (long long)gk * Nc + gj);
                    vv[0] = v.x; vv[1] = v.y; vv[2] = v.z; vv[3] = v.w;
                }
            } else {
                if (gk < K) {
                    int n = bn[it], h = bh[it];
                    #pragma unroll
                    for (int e = 0; e < 4; ++e) {
                        if (gj + e < Nc) vv[e] = Bm[((long long)n * K + gk) * Hh + h];
                        if (++h >= Hh) { h = 0; ++n; }
                    }
                }
            }
            #pragma unroll
            for (int e = 0; e < 4; ++e) {
                bf16 h, l; split2(vv[e], h, l);
                sBh[(g * 4 + e) * BS_STR + k] = h;
                sBl[(g * 4 + e) * BS_STR + k] = l;
            }
        }
        __syncthreads();

        #pragma unroll
        for (int ks = 0; ks < 4; ++ks) {
            const int kcol = ks * 16 + qid * 2;
            // B fragments for this ks (16 regs)
            uint32_t bhf[4][2], blf[4][2];
            #pragma unroll
            for (int ni = 0; ni < 4; ++ni) {
                const int n = wn + ni * 8 + gid;
                bhf[ni][0] = *(const uint32_t*)(sBh + n * BS_STR + kcol);
                bhf[ni][1] = *(const uint32_t*)(sBh + n * BS_STR + kcol + 8);
                blf[ni][0] = *(const uint32_t*)(sBl + n * BS_STR + kcol);
                blf[ni][1] = *(const uint32_t*)(sBl + n * BS_STR + kcol + 8);
            }
            // A fragments one m-tile at a time (8 regs live)
            #pragma unroll
            for (int mi = 0; mi < 2; ++mi) {
                const int r = wm + mi * 16 + gid;
                uint32_t ah0 = *(const uint32_t*)(sAh + r * AS_STR + kcol);
                uint32_t ah1 = *(const uint32_t*)(sAh + (r + 8) * AS_STR + kcol);
                uint32_t ah2 = *(const uint32_t*)(sAh + r * AS_STR + kcol + 8);
                uint32_t ah3 = *(const uint32_t*)(sAh + (r + 8) * AS_STR + kcol + 8);
                uint32_t al0 = *(const uint32_t*)(sAl + r * AS_STR + kcol);
                uint32_t al1 = *(const uint32_t*)(sAl + (r + 8) * AS_STR + kcol);
                uint32_t al2 = *(const uint32_t*)(sAl + r * AS_STR + kcol + 8);
                uint32_t al3 = *(const uint32_t*)(sAl + (r + 8) * AS_STR + kcol + 8);
                #pragma unroll
                for (int ni = 0; ni < 4; ++ni) {
                    mma_bf16(acc[mi][ni], ah0, ah1, ah2, ah3, bhf[ni][0], bhf[ni][1]);
                    mma_bf16(acc[mi][ni], ah0, ah1, ah2, ah3, blf[ni][0], blf[ni][1]);
                    mma_bf16(acc[mi][ni], al0, al1, al2, al3, bhf[ni][0], bhf[ni][1]);
                }
            }
        }
    }

    float* Cz = C + (long long)z * Rows * Nc;
    #pragma unroll
    for (int mi = 0; mi < 2; ++mi) {
        const int r0 = m0 + wm + mi * 16 + gid;
        #pragma unroll
        for (int ni = 0; ni < 4; ++ni) {
            const int cn = j0 + wn + ni * 8 + qid * 2;
            if (cn < Nc) {
                float2 lo2 = make_float2(acc[mi][ni][0], acc[mi][ni][1]);
                float2 hi2 = make_float2(acc[mi][ni][2], acc[mi][ni][3]);
                *(float2*)(Cz + (long long)r0 * Nc + cn)       = lo2;
                *(float2*)(Cz + (long long)(r0 + 8) * Nc + cn) = hi2;
            }
        }
    }
}

// ---------------- TENSOR fused: full-h per block, pre-split Dw/Cw, prefetch ----------------
#define XH_STR 18
#define FG_SXH 0
#define FG_SXL (FG_SXH + HhP*XH_STR*2)
#define FG_SHH (FG_SXL + HhP*XH_STR*2)
#define FG_SHL (FG_SHH + HhP*XH_STR*2)
#define FG_SB   (FG_SHL + HhP*XH_STR*2)
#define FG_SMEM (FG_SB + HhP*4)          /* 101824 */
#define NTILE 86

__global__ __launch_bounds__(256, 2) void fused_G_tc(const float* __restrict__ XW1,
                                                     const bf16* __restrict__ dwh,
                                                     const bf16* __restrict__ dwl,
                                                     const bf16* __restrict__ chh,
                                                     const bf16* __restrict__ chl,
                                                     const float* __restrict__ b1,
                                                     bf16* __restrict__ gh,
                                                     bf16* __restrict__ gl)
{
    extern __shared__ __align__(16) char sm[];
    bf16*  sXh = (bf16*)(sm + FG_SXH);
    bf16*  sXl = (bf16*)(sm + FG_SXL);
    bf16*  sHh = (bf16*)(sm + FG_SHH);
    bf16*  sHl = (bf16*)(sm + FG_SHL);
    float* sb  = (float*)(sm + FG_SB);

    const int bx = blockIdx.x;
    const int n  = bx & (Ne - 1);
    const int b  = bx >> 4;
    const int t = threadIdx.x;
    const int w = t >> 5, lane = t & 31;
    const int gid = lane >> 2, qid = lane & 3;
    const long long mstep = (long long)NHt;

    for (int h = t; h < HhP; h += 256)
        sb[h] = (h < Hh) ? b1[n * Hh + h] : 0.f;

    #pragma unroll 1
    for (int mm = 0; mm < Mt; ++mm) {
        const long long rb = ((long long)(b * Mt + mm) * Ne + n) * Hh;
        for (int h = t; h < HhP; h += 256) {
            const float v = (h < Hh) ? XW1[rb + h] : 0.f;
            bf16 hi, lo; split2(v, hi, lo);
            sXh[h * XH_STR + mm] = hi;
            sXl[h * XH_STR + mm] = lo;
        }
    }
    __syncthreads();

    float acc[11][4];
    #pragma unroll
    for (int i = 0; i < 11; ++i)
        #pragma unroll
        for (int e = 0; e < 4; ++e) acc[i][e] = 0.f;

    const int NCH = 43;
    const long long dwbn = (long long)(b * Ne + n) * HhP * Mt;
    const int moff = qid * 2;
    const long long c0r = ((long long)(b * Mt + gid) * Ne + n) * Hh;
    const long long c8r = c0r + 8 * mstep;

    uint32_t dah[4], dal[4], cah[4], cal[4];
    {
        const long long r0 = dwbn + (long long)gid * Mt + moff;
        const long long r8 = r0 + 8 * Mt;
        dah[0] = *(const uint32_t*)(dwh + r0);
        dah[1] = *(const uint32_t*)(dwh + r8);
        dah[2] = *(const uint32_t*)(dwh + r0 + 8);
        dah[3] = *(const uint32_t*)(dwh + r8 + 8);
        dal[0] = *(const uint32_t*)(dwl + r0);
        dal[1] = *(const uint32_t*)(dwl + r8);
        dal[2] = *(const uint32_t*)(dwl + r0 + 8);
        dal[3] = *(const uint32_t*)(dwl + r8 + 8);
        const int k0 = qid * 2, k8 = k0 + 8;
        cah[0] = *(const uint32_t*)(chh + c0r + k0);
        cal[0] = *(const uint32_t*)(chl + c0r + k0);
        cah[1] = *(const uint32_t*)(chh + c8r + k0);
        cal[1] = *(const uint32_t*)(chl + c8r + k0);
        cah[2] = *(const uint32_t*)(chh + c0r + k8);
        cal[2] = *(const uint32_t*)(chl + c0r + k8);
        cah[3] = *(const uint32_t*)(chh + c8r + k8);
        cal[3] = *(const uint32_t*)(chl + c8r + k8);
    }

    for (int c = 0; c < NCH; ++c) {
        uint32_t ndah[4], ndal[4], ncah[4], ncal[4];
        if (c + 1 < NCH) {
            const int P0 = (c + 1) * 16;
            const long long r0 = dwbn + (long long)(P0 + gid) * Mt + moff;
            const long long r8 = r0 + 8 * Mt;
            ndah[0] = *(const uint32_t*)(dwh + r0);
            ndah[1] = *(const uint32_t*)(dwh + r8);
            ndah[2] = *(const uint32_t*)(dwh + r0 + 8);
            ndah[3] = *(const uint32_t*)(dwh + r8 + 8);
            ndal[0] = *(const uint32_t*)(dwl + r0);
            ndal[1] = *(const uint32_t*)(dwl + r8);
            ndal[2] = *(const uint32_t*)(dwl + r0 + 8);
            ndal[3] = *(const uint32_t*)(dwl + r8 + 8);
            const int k0 = P0 + qid * 2, k8 = k0 + 8;
            if (k0 + 1 < Hh) {
                ncah[0] = *(const uint32_t*)(chh + c0r + k0);
                ncal[0] = *(const uint32_t*)(chl + c0r + k0);
                ncah[1] = *(const uint32_t*)(chh + c8r + k0);
                ncal[1] = *(const uint32_t*)(chl + c8r + k0);
            } else { ncah[0] = ncal[0] = ncah[1] = ncal[1] = 0; }
            if (k8 + 1 < Hh) {
                ncah[2] = *(const uint32_t*)(chh + c0r + k8);
                ncal[2] = *(const uint32_t*)(chl + c0r + k8);
                ncah[3] = *(const uint32_t*)(chh + c8r + k8);
                ncal[3] = *(const uint32_t*)(chl + c8r + k8);
            } else { ncah[2] = ncal[2] = ncah[3] = ncal[3] = 0; }
        } else {
            #pragma unroll
            for (int i = 0; i < 4; ++i) { ndah[i] = ndal[i] = ncah[i] = ncal[i] = 0; }
        }

        #pragma unroll
        for (int ti = 0; ti < 11; ++ti) {
            const int tw = w + ti * 8;
            if (tw >= NTILE) break;
            const int hrow = tw * 8 + gid;
            const uint32_t xh0 = *(const uint32_t*)(sXh + hrow * XH_STR + qid * 2);
            const uint32_t xh1 = *(const uint32_t*)(sXh + hrow * XH_STR + qid * 2 + 8);
            const uint32_t xl0 = *(const uint32_t*)(sXl + hrow * XH_STR + qid * 2);
            const uint32_t xl1 = *(const uint32_t*)(sXl + hrow * XH_STR + qid * 2 + 8);
            float cf[4] = {0.f, 0.f, 0.f, 0.f};
            mma_bf16(cf, dah[0], dah[1], dah[2], dah[3], xh0, xh1);
            mma_bf16(cf, dah[0], dah[1], dah[2], dah[3], xl0, xl1);
            mma_bf16(cf, dal[0], dal[1], dal[2], dal[3], xh0, xh1);
            const int ha = tw * 8 + qid * 2, hb = ha + 1;
            const float ba = sb[ha], bb = sb[hb];
            const float v00 = fmaxf(cf[0] + ba, 0.f);
            const float v01 = fmaxf(cf[1] + bb, 0.f);
            const float v10 = fmaxf(cf[2] + ba, 0.f);
            const float v11 = fmaxf(cf[3] + bb, 0.f);
            bf16 hi, lo;
            split2(v00, hi, lo); sHh[ha * XH_STR + gid]     = hi; sHl[ha * XH_STR + gid]     = lo;
            split2(v01, hi, lo); sHh[hb * XH_STR + gid]     = hi; sHl[hb * XH_STR + gid]     = lo;
            split2(v10, hi, lo); sHh[ha * XH_STR + gid + 8] = hi; sHl[ha * XH_STR + gid + 8] = lo;
            split2(v11, hi, lo); sHh[hb * XH_STR + gid + 8] = hi; sHl[hb * XH_STR + gid + 8] = lo;
        }
        __syncwarp();

        #pragma unroll
        for (int ti = 0; ti < 11; ++ti) {
            const int tw = w + ti * 8;
            if (tw >= NTILE) break;
            const int hrow = tw * 8 + gid;
            const uint32_t hh0 = *(const uint32_t*)(sHh + hrow * XH_STR + qid * 2);
            const uint32_t hh1 = *(const uint32_t*)(sHh + hrow * XH_STR + qid * 2 + 8);
            const uint32_t hl0 = *(const uint32_t*)(sHl + hrow * XH_STR + qid * 2);
            const uint32_t hl1 = *(const uint32_t*)(sHl + hrow * XH_STR + qid * 2 + 8);
            mma_bf16(acc[ti], cah[0], cah[1], cah[2], cah[3], hh0, hh1);
            mma_bf16(acc[ti], cah[0], cah[1], cah[2], cah[3], hl0, hl1);
            mma_bf16(acc[ti], cal[0], cal[1], cal[2], cal[3], hh0, hh1);
        }
        __syncwarp();

        #pragma unroll
        for (int i = 0; i < 4; ++i) {
            dah[i] = ndah[i]; dal[i] = ndal[i];
            cah[i] = ncah[i]; cal[i] = ncal[i];
        }
    }

    const long long g0 = ((long long)(b * Mt + gid) * Ne + n) * Hh;
    const long long g8 = g0 + 8 * mstep;
    #pragma unroll
    for (int ti = 0; ti < 11; ++ti) {
        const int tw = w + ti * 8;
        if (tw >= NTILE) break;
        const int ha = tw * 8 + qid * 2, hb = ha + 1;
        if (ha < Hh) {
            st_split(gh, gl, g0 + ha, acc[ti][0]);
            st_split(gh, gl, g8 + ha, acc[ti][2]);
        }
        if (hb < Hh) {
            st_split(gh, gl, g0 + hb, acc[ti][1]);
            st_split(gh, gl, g8 + hb, acc[ti][3]);
        }
    }
}

// ---------------- ypart_reduce ----------------
__global__ void ypart_reduce(const float* __restrict__ part, const float* __restrict__ b2s,
                             float* __restrict__ Y)
{
    const int i4 = blockIdx.x * blockDim.x + threadIdx.x;
    const int idx = i4 * 4;
    const int col = idx & (OUTD - 1);
    float4 s = *(const float4*)(b2s + col);
    #pragma unroll
    for (int z = 0; z < YSPLIT; ++z) {
        float4 p = *(const float4*)(part + z * (Rows * OUTD) + idx);
        s.x += p.x; s.y += p.y; s.z += p.z; s.w += p.w;
    }
    *(float4*)(Y + idx) = s;
}

// ---------------- output GEMM ----------------
__global__ __launch_bounds__(128) void out_partial(const float* __restrict__ Y,
                                                   const float* __restrict__ Wout,
                                                   float* __restrict__ part)
{
    constexpr int KC = (Mt * Dd) / OSPLIT;
    __shared__ float ys[Bb][KC];
    const int tid = threadIdx.x;
    const int col = tid * 4;
    const int k0  = blockIdx.y * KC;

    for (int idx = tid; idx < Bb * KC; idx += 128) {
        const int bi = idx / KC, kk = idx - bi * KC;
        ys[bi][kk] = Y[bi * (Mt * Dd) + k0 + kk];
    }
    __syncthreads();

    float4 acc[Bb];
    #pragma unroll
    for (int bi = 0; bi < Bb; ++bi) acc[bi] = make_float4(0.f,0.f,0.f,0.f);

    for (int kk = 0; kk < KC; ++kk) {
        const float4 w = *(const float4*)(Wout + (k0 + kk) * OUTD + col);
        #pragma unroll
        for (int bi = 0; bi < Bb; ++bi) {
            const float yv = ys[bi][kk];
            acc[bi].x = fmaf(yv, w.x, acc[bi].x);
            acc[bi].y = fmaf(yv, w.y, acc[bi].y);
            acc[bi].z = fmaf(yv, w.z, acc[bi].z);
            acc[bi].w = fmaf(yv, w.w, acc[bi].w);
        }
    }
    #pragma unroll
    for (int bi = 0; bi < Bb; ++bi)
        *(float4*)(part + (blockIdx.y * Bb + bi) * OUTD + col) = acc[bi];
}

__global__ void out_reduce(const float* __restrict__ part, const float* __restrict__ bout,
                           float* __restrict__ out)
{
    const int i4 = blockIdx.x * blockDim.x + threadIdx.x;
    const int idx = i4 * 4;
    const int col = idx & (OUTD - 1);
    const int bi  = idx >> 9;
    float4 s = *(const float4*)(bout + col);
    #pragma unroll
    for (int z = 0; z < OSPLIT; ++z) {
        float4 p = *(const float4*)(part + (z * Bb + bi) * OUTD + col);
        s.x += p.x; s.y += p.y; s.z += p.z; s.w += p.w;
    }
    *(float4*)(out + idx) = s;
}

// ---------------- launch ----------------
extern "C" void kernel_launch(void* const* d_in, const int* in_sizes, int n_in,
                              void* d_out, int out_size)
{
    const float* x    = (const float*)d_in[0];
    const float* phi  = (const float*)d_in[1];
    const float* W1   = (const float*)d_in[2];
    const float* b1   = (const float*)d_in[3];
    const float* W2   = (const float*)d_in[4];
    const float* b2   = (const float*)d_in[5];
    const float* Wout = (const float*)d_in[6];
    const float* bout = (const float*)d_in[7];
    float* out = (float*)d_out;

    float *p_logits, *p_XW1, *p_Ypart, *p_Y, *p_b2sum, *p_opart;
    bf16 *p_xh, *p_xl, *p_gh, *p_gl, *p_chh, *p_chl, *p_dwh, *p_dwl;
    cudaGetSymbolAddress((void**)&p_logits, g_logits);
    cudaGetSymbolAddress((void**)&p_XW1,    g_XW1);
    cudaGetSymbolAddress((void**)&p_Ypart,  g_Ypart);
    cudaGetSymbolAddress((void**)&p_Y,      g_Y);
    cudaGetSymbolAddress((void**)&p_b2sum,  g_b2sum);
    cudaGetSymbolAddress((void**)&p_opart,  g_opart);
    cudaGetSymbolAddress((void**)&p_xh,   g_xh);
    cudaGetSymbolAddress((void**)&p_xl,   g_xl);
    cudaGetSymbolAddress((void**)&p_gh,   g_gh);
    cudaGetSymbolAddress((void**)&p_gl,   g_gl);
    cudaGetSymbolAddress((void**)&p_chh,  g_chh);
    cudaGetSymbolAddress((void**)&p_chl,  g_chl);
    cudaGetSymbolAddress((void**)&p_dwh,  g_dwh);
    cudaGetSymbolAddress((void**)&p_dwl,  g_dwl);

    cudaFuncSetAttribute(mma_gemm<0>, cudaFuncAttributeMaxDynamicSharedMemorySize, MG_SMEM);
    cudaFuncSetAttribute(mma_gemm<1>, cudaFuncAttributeMaxDynamicSharedMemorySize, MG_SMEM);
    cudaFuncSetAttribute(fused_G_tc,  cudaFuncAttributeMaxDynamicSharedMemorySize, FG_SMEM);

    const dim3 gBig((NHt + 63)/64, Rows/128, 1);             // 171 x 2

    prep_k<<<CVT_BLOCKS + 2, 256>>>(x, p_xh, p_xl, b2, p_b2sum);                 // 1
    mma_gemm<0><<<gBig, 256, MG_SMEM>>>(p_xh, p_xl, phi, p_logits, NHt, Dd, 1);  // 2
    softdw<<<Rows + (Bb*Ne*HhP)/256, 256>>>(p_logits, p_chh, p_chl, p_dwh, p_dwl); // 3
    mma_gemm<1><<<gBig, 256, MG_SMEM>>>(p_xh, p_xl, W1, p_XW1, NHt, Dd, 1);      // 4 (profiled)

    fused_G_tc<<<Bb*Ne, 256, FG_SMEM>>>(p_XW1, p_dwh, p_dwl, p_chh, p_chl, b1, p_gh, p_gl); // 5

    const dim3 gY(OUTD/64, Rows/128, YSPLIT);                // 8 x 2 x 16
    mma_gemm<0><<<gY, 256, MG_SMEM>>>(p_gh, p_gl, W2, p_Ypart, OUTD, NHt, YSPLIT); // 6
    ypart_reduce<<<(Rows*OUTD/4)/256, 256>>>(p_Ypart, p_b2sum, p_Y);             // 7

    const dim3 gO(1, OSPLIT, 1);
    out_partial<<<gO, 128>>>(p_Y, Wout, p_opart);                                 // 8
    out_reduce <<<(Bb*OUTD/4)/256, 256>>>(p_opart, bout, out);                    // 9
}

// round 15
// speedup vs baseline: 1.6833x; 1.0222x over previous
#include <cuda_runtime.h>
#include <cuda_bf16.h>
#include <math.h>
#include <stdint.h>

#define Bb   16
#define Mt   16
#define Dd   512
#define Ne   16
#define Hh   682
#define HhP  688          /* padded p extent */
#define NHt  (Ne*Hh)      /* 10912 */
#define Rows (Bb*Mt)      /* 256   */
#define OUTD 512
#define YSPLIT 16
#define OSPLIT 64

typedef unsigned long long ull;
typedef __nv_bfloat16 bf16;

// ---- warp mma: D(16x8 f32) += A(16x16 bf16) * B(16x8 bf16) ----
__device__ __forceinline__ void mma_bf16(float* c, uint32_t a0, uint32_t a1, uint32_t a2, uint32_t a3,
                                         uint32_t b0, uint32_t b1) {
    asm volatile("mma.sync.aligned.m16n8k16.row.col.f32.bf16.bf16.f32 "
        "{%0,%1,%2,%3}, {%4,%5,%6,%7}, {%8,%9}, {%0,%1,%2,%3};"
        : "+f"(c[0]), "+f"(c[1]), "+f"(c[2]), "+f"(c[3])
        : "r"(a0), "r"(a1), "r"(a2), "r"(a3), "r"(b0), "r"(b1));
}

__device__ __forceinline__ void split2(float v, bf16& h, bf16& l) {
    h = __float2bfloat16(v);
    l = __float2bfloat16(v - __bfloat162float(h));
}
__device__ __forceinline__ void st_split(bf16* gh, bf16* gl, long long idx, float v) {
    bf16 h, l; split2(v, h, l);
    gh[idx] = h; gl[idx] = l;
}

// ---- cp.async helpers ----
__device__ __forceinline__ uint32_t smem_u32(const void* p) {
    uint32_t a;
    asm("{ .reg .u64 t; cvta.to.shared.u64 t, %1; cvt.u32.u64 %0, t; }" : "=r"(a) : "l"(p));
    return a;
}
__device__ __forceinline__ void cp_async8(uint32_t dst, const void* src, int srcsz) {
    asm volatile("cp.async.ca.shared.global [%0], [%1], 8, %2;" :: "r"(dst), "l"(src), "r"(srcsz));
}
#define CP_COMMIT() asm volatile("cp.async.commit_group;" ::: "memory")
#define CP_WAIT0()  asm volatile("cp.async.wait_group 0;" ::: "memory")

// ---------------- scratch ----------------
__device__ float g_logits[Rows*NHt];
__device__ float g_XW1[Rows*NHt];
__device__ float g_Ypart[YSPLIT*Rows*OUTD];
__device__ float g_Y[Rows*OUTD];
__device__ float g_b2sum[OUTD];
__device__ float g_opart[OSPLIT*Bb*OUTD];
__device__ bf16 g_xh[Rows*Dd],  g_xl[Rows*Dd];
__device__ bf16 g_gh[Rows*NHt], g_gl[Rows*NHt];
__device__ bf16 g_chh[Rows*NHt], g_chl[Rows*NHt];
__device__ bf16 g_dwh[Bb*Ne*HhP*Mt], g_dwl[Bb*Ne*HhP*Mt];

// ---------------- prep: x split + b2sum ----------------
#define CVT_BLOCKS (Rows*Dd/4/256)      /* 128 */
__global__ void prep_k(const float* __restrict__ src, bf16* __restrict__ hi,
                       bf16* __restrict__ lo, const float* __restrict__ b2,
                       float* __restrict__ b2s)
{
    const int bx = blockIdx.x;
    if (bx < CVT_BLOCKS) {
        const int i = bx * 256 + threadIdx.x;
        const float4 v = ((const float4*)src)[i];
        bf16 h[4], l[4];
        const float vv[4] = {v.x, v.y, v.z, v.w};
        #pragma unroll
        for (int e = 0; e < 4; ++e) split2(vv[e], h[e], l[e]);
        *(ull*)(hi + i * 4) = *(const ull*)h;
        *(ull*)(lo + i * 4) = *(const ull*)l;
    } else {
        const int d = (bx - CVT_BLOCKS) * 256 + threadIdx.x;
        if (d < OUTD) {
            float s = 0.f;
            #pragma unroll
            for (int n = 0; n < Ne; ++n) s += b2[n * OUTD + d];
            b2s[d] = s;
        }
    }
}

// ---------------- combined: softmax_np (blocks 0..255) + dw_split (blocks 256..943) ----------------
__global__ void softdw(const float* __restrict__ L, bf16* __restrict__ chh,
                       bf16* __restrict__ chl, bf16* __restrict__ dwh,
                       bf16* __restrict__ dwl)
{
    __shared__ float s[Ne * 688];
    const int tid = threadIdx.x;

    if (blockIdx.x < Rows) {
        const int bm = blockIdx.x;
        const float* Lrow = L + bm * NHt;

        for (int i4 = tid; i4 < NHt / 4; i4 += 256) {
            const float4 v = *(const float4*)(Lrow + i4 * 4);
            const int idx = i4 * 4;
            const int n = idx / Hh;
            const int p = idx - n * Hh;
            float vv[4] = {v.x, v.y, v.z, v.w};
            int nn = n, pp = p;
            #pragma unroll
            for (int e = 0; e < 4; ++e) {
                s[nn * 688 + pp] = vv[e];
                if (++pp >= Hh) { pp = 0; ++nn; }
            }
        }
        __syncthreads();

        for (int p = tid; p < Hh; p += 256) {
            float mx = -3.4e38f;
            #pragma unroll
            for (int n = 0; n < Ne; ++n) mx = fmaxf(mx, s[n * 688 + p]);
            float sum = 0.f;
            #pragma unroll
            for (int n = 0; n < Ne; ++n) {
                const float e = expf(s[n * 688 + p] - mx);
                s[n * 688 + p] = e;
                sum += e;
            }
            const float inv = 1.f / sum;
            #pragma unroll
            for (int n = 0; n < Ne; ++n) s[n * 688 + p] *= inv;
        }
        __syncthreads();

        const int warp = tid >> 5, lane = tid & 31;
        for (int n = warp; n < Ne; n += 8) {
            float mx = -3.4e38f;
            for (int p = lane; p < Hh; p += 32) mx = fmaxf(mx, s[n * 688 + p]);
            #pragma unroll
            for (int o = 16; o; o >>= 1) mx = fmaxf(mx, __shfl_xor_sync(0xffffffffu, mx, o));
            float sum = 0.f;
            for (int p = lane; p < Hh; p += 32) {
                const float e = expf(s[n * 688 + p] - mx);
                s[n * 688 + p] = e;
                sum += e;
            }
            #pragma unroll
            for (int o = 16; o; o >>= 1) sum += __shfl_xor_sync(0xffffffffu, sum, o);
            const float inv = 1.f / sum;
            for (int p = lane; p < Hh; p += 32) {
                bf16 h, l; split2(s[n * 688 + p] * inv, h, l);
                const long long o2 = (long long)bm * NHt + n * Hh + p;
                chh[o2] = h; chl[o2] = l;
            }
        }
    } else {
        const int col = (blockIdx.x - Rows) * 256 + tid;
        const int p  = col % HhP;
        const int bn = col / HhP;
        const int b  = bn >> 4;
        const int n  = bn & (Ne - 1);

        bf16 h[Mt], l[Mt];
        if (p < Hh) {
            const long long base = ((long long)(b * Mt) * Ne + n) * Hh + p;
            float v[Mt], mx = -3.4e38f;
            #pragma unroll
            for (int m = 0; m < Mt; ++m) { v[m] = L[base + (long long)m * NHt]; mx = fmaxf(mx, v[m]); }
            float sum = 0.f;
            #pragma unroll
            for (int m = 0; m < Mt; ++m) { v[m] = expf(v[m] - mx); sum += v[m]; }
            const float inv = 1.f / sum;
            #pragma unroll
            for (int m = 0; m < Mt; ++m) split2(v[m] * inv, h[m], l[m]);
        } else {
            #pragma unroll
            for (int m = 0; m < Mt; ++m) { h[m] = __float2bfloat16(0.f); l[m] = h[m]; }
        }
        const long long o = (long long)col * Mt;
        #pragma unroll
        for (int q = 0; q < 4; ++q) {
            *(ull*)(dwh + o + q * 4) = *(const ull*)(h + q * 4);
            *(ull*)(dwl + o + q * 4) = *(const ull*)(l + q * 4);
        }
    }
}

// ---------------- mma.sync bf16-split GEMM, cp.async double-buffered ----------------
#define AS_STR 72
#define BS_STR 74
#define ABUF (128*AS_STR*2)   /* 18432 bytes per A plane */
#define BBUF (64*BS_STR*2)    /* 9472  bytes per B plane */
#define STG_AH 0
#define STG_AL (STG_AH + ABUF)
#define STG_BH (STG_AL + ABUF)
#define STG_BL (STG_BH + BBUF)
#define STAGE  (STG_BL + BBUF)           /* 55808 */
#define MG_SMEM (2*STAGE)                /* 111616 */

template<int MODE>
__global__ __launch_bounds__(256, 2) void mma_gemm(
    const bf16* __restrict__ Ah, const bf16* __restrict__ Al,
    const float* __restrict__ Bm,
    float* __restrict__ C, int Nc, int K, int nsplit)
{
    extern __shared__ __align__(16) char sm[];
    const uint32_t smb = smem_u32(sm);

    const int t = threadIdx.x;
    const int lane = t & 31, warp = t >> 5;
    const int wm = (warp & 3) * 32;
    const int wn = (warp >> 2) * 32;
    const int m0 = blockIdx.y * 128;
    const int j0 = blockIdx.x * 64;
    const int z  = blockIdx.z;
    const int nch = (K + 63) >> 6;
    const int c0 = (int)((long long)nch * z / nsplit);
    const int c1 = (int)((long long)nch * (z + 1) / nsplit);

    float acc[2][4][4];
    #pragma unroll
    for (int i = 0; i < 2; ++i)
        #pragma unroll
        for (int j = 0; j < 4; ++j)
            #pragma unroll
            for (int e = 0; e < 4; ++e) acc[i][j][e] = 0.f;

    const int gid = lane >> 2;
    const int qid = lane & 3;

    // loader geometry
    const int a_kq = t & 15, a_row = t >> 4;               // A: slot per it
    int bn[4], bh[4];
    if (MODE == 1) {
        #pragma unroll
        for (int it = 0; it < 4; ++it) {
            const int g = (t + it * 256) & 15;
            const int j = j0 + g * 4;
            int n = j / Hh;
            bn[it] = n;
            bh[it] = j - n * Hh;
        }
    }

    // ---- prologue: load chunk c0 into stage 0
    {
        const int k0 = c0 << 6;
        const uint32_t sAh = smb + STG_AH, sAl = smb + STG_AL;
        #pragma unroll
        for (int it = 0; it < 8; ++it) {
            const int s = t + it * 256;
            const int kq = s & 15, row = s >> 4;
            const int gk = k0 + kq * 4;
            const long long ga = (long long)(m0 + row) * K + gk;
            const int sz = (gk + 4 <= K) ? 8 : 0;
            const uint32_t ofs = (row * AS_STR + kq * 4) * 2;
            cp_async8(sAh + ofs, Ah + ga, sz);
            cp_async8(sAl + ofs, Al + ga, sz);
        }
        CP_COMMIT();
        bf16* sBh = (bf16*)(sm + STG_BH);
        bf16* sBl = (bf16*)(sm + STG_BL);
        #pragma unroll
        for (int it = 0; it < 4; ++it) {
            const int s = t + it * 256;
            const int g = s & 15, k = s >> 4;
            const int gj = j0 + g * 4;
            const int gk = k0 + k;
            float vv[4] = {0.f, 0.f, 0.f, 0.f};
            if (MODE == 0) {
                if (gj + 4 <= Nc && gk < K) {
                    const float4 v = *(const float4*)(Bm + (long long)gk * Nc + gj);
                    vv[0] = v.x; vv[1] = v.y; vv[2] = v.z; vv[3] = v.w;
                }
            } else {
                if (gk < K) {
                    int n = bn[it], h = bh[it];
                    #pragma unroll
                    for (int e = 0; e < 4; ++e) {
                        if (gj + e < Nc) vv[e] = Bm[((long long)n * K + gk) * Hh + h];
                        if (++h >= Hh) { h = 0; ++n; }
                    }
                }
            }
            #pragma unroll
            for (int e = 0; e < 4; ++e) {
                bf16 h, l; split2(vv[e], h, l);
                sBh[(g * 4 + e) * BS_STR + k] = h;
                sBl[(g * 4 + e) * BS_STR + k] = l;
            }
        }
        CP_WAIT0();
        __syncthreads();
    }

    for (int c = c0; c < c1; ++c) {
        const int cur = (c - c0) & 1;
        const int nxt = cur ^ 1;
        const char* smc = sm + cur * STAGE;

        // ---- issue loads for chunk c+1 into nxt stage (A via cp.async, B scalar)
        if (c + 1 < c1) {
            const int k0 = (c + 1) << 6;
            const uint32_t sAh = smb + nxt * STAGE + STG_AH;
            const uint32_t sAl = smb + nxt * STAGE + STG_AL;
            #pragma unroll
            for (int it = 0; it < 8; ++it) {
                const int s = t + it * 256;
                const int kq = s & 15, row = s >> 4;
                const int gk = k0 + kq * 4;
                const long long ga = (long long)(m0 + row) * K + gk;
                const int sz = (gk + 4 <= K) ? 8 : 0;
                const uint32_t ofs = (row * AS_STR + kq * 4) * 2;
                cp_async8(sAh + ofs, Ah + ga, sz);
                cp_async8(sAl + ofs, Al + ga, sz);
            }
            CP_COMMIT();
            bf16* sBh = (bf16*)(sm + nxt * STAGE + STG_BH);
            bf16* sBl = (bf16*)(sm + nxt * STAGE + STG_BL);
            #pragma unroll
            for (int it = 0; it < 4; ++it) {
                const int s = t + it * 256;
                const int g = s & 15, k = s >> 4;
                const int gj = j0 + g * 4;
                const int gk = k0 + k;
                float vv[4] = {0.f, 0.f, 0.f, 0.f};
                if (MODE == 0) {
                    if (gj + 4 <= Nc && gk < K) {
                        const float4 v = *(const float4*)(Bm + (long long)gk * Nc + gj);
                        vv[0] = v.x; vv[1] = v.y; vv[2] = v.z; vv[3] = v.w;
                    }
                } else {
                    if (gk < K) {
                        int n = bn[it], h = bh[it];
                        #pragma unroll
                        for (int e = 0; e < 4; ++e) {
                            if (gj + e < Nc) vv[e] = Bm[((long long)n * K + gk) * Hh + h];
                            if (++h >= Hh) { h = 0; ++n; }
                        }
                    }
                }
                #pragma unroll
                for (int e = 0; e < 4; ++e) {
                    bf16 h, l; split2(vv[e], h, l);
                    sBh[(g * 4 + e) * BS_STR + k] = h;
                    sBl[(g * 4 + e) * BS_STR + k] = l;
                }
            }
        }

        // ---- compute chunk c from cur stage
        const bf16* sAh = (const bf16*)(smc + STG_AH);
        const bf16* sAl = (const bf16*)(smc + STG_AL);
        const bf16* sBh = (const bf16*)(smc + STG_BH);
        const bf16* sBl = (const bf16*)(smc + STG_BL);

        #pragma unroll
        for (int ks = 0; ks < 4; ++ks) {
            const int kcol = ks * 16 + qid * 2;
            uint32_t bhf[4][2], blf[4][2];
            #pragma unroll
            for (int ni = 0; ni < 4; ++ni) {
                const int n = wn + ni * 8 + gid;
                bhf[ni][0] = *(const uint32_t*)(sBh + n * BS_STR + kcol);
                bhf[ni][1] = *(const uint32_t*)(sBh + n * BS_STR + kcol + 8);
                blf[ni][0] = *(const uint32_t*)(sBl + n * BS_STR + kcol);
                blf[ni][1] = *(const uint32_t*)(sBl + n * BS_STR + kcol + 8);
            }
            #pragma unroll
            for (int mi = 0; mi < 2; ++mi) {
                const int r = wm + mi * 16 + gid;
                uint32_t ah0 = *(const uint32_t*)(sAh + r * AS_STR + kcol);
                uint32_t ah1 = *(const uint32_t*)(sAh + (r + 8) * AS_STR + kcol);
                uint32_t ah2 = *(const uint32_t*)(sAh + r * AS_STR + kcol + 8);
                uint32_t ah3 = *(const uint32_t*)(sAh + (r + 8) * AS_STR + kcol + 8);
                uint32_t al0 = *(const uint32_t*)(sAl + r * AS_STR + kcol);
                uint32_t al1 = *(const uint32_t*)(sAl + (r + 8) * AS_STR + kcol);
                uint32_t al2 = *(const uint32_t*)(sAl + r * AS_STR + kcol + 8);
                uint32_t al3 = *(const uint32_t*)(sAl + (r + 8) * AS_STR + kcol + 8);
                #pragma unroll
                for (int ni = 0; ni < 4; ++ni) {
                    mma_bf16(acc[mi][ni], ah0, ah1, ah2, ah3, bhf[ni][0], bhf[ni][1]);
                    mma_bf16(acc[mi][ni], ah0, ah1, ah2, ah3, blf[ni][0], blf[ni][1]);
                    mma_bf16(acc[mi][ni], al0, al1, al2, al3, bhf[ni][0], bhf[ni][1]);
                }
            }
        }

        if (c + 1 < c1) CP_WAIT0();
        __syncthreads();
    }

    float* Cz = C + (long long)z * Rows * Nc;
    #pragma unroll
    for (int mi = 0; mi < 2; ++mi) {
        const int r0 = m0 + wm + mi * 16 + gid;
        #pragma unroll
        for (int ni = 0; ni < 4; ++ni) {
            const int cn = j0 + wn + ni * 8 + qid * 2;
            if (cn < Nc) {
                float2 lo2 = make_float2(acc[mi][ni][0], acc[mi][ni][1]);
                float2 hi2 = make_float2(acc[mi][ni][2], acc[mi][ni][3]);
                *(float2*)(Cz + (long long)r0 * Nc + cn)       = lo2;
                *(float2*)(Cz + (long long)(r0 + 8) * Nc + cn) = hi2;
            }
        }
    }
}

// ---------------- TENSOR fused: full-h per block, pre-split Dw/Cw, prefetch ----------------
#define XH_STR 18
#define FG_SXH 0
#define FG_SXL (FG_SXH + HhP*XH_STR*2)
#define FG_SHH (FG_SXL + HhP*XH_STR*2)
#define FG_SHL (FG_SHH + HhP*XH_STR*2)
#define FG_SB   (FG_SHL + HhP*XH_STR*2)
#define FG_SMEM (FG_SB + HhP*4)          /* 101824 */
#define NTILE 86

__global__ __launch_bounds__(256, 2) void fused_G_tc(const float* __restrict__ XW1,
                                                     const bf16* __restrict__ dwh,
                                                     const bf16* __restrict__ dwl,
                                                     const bf16* __restrict__ chh,
                                                     const bf16* __restrict__ chl,
                                                     const float* __restrict__ b1,
                                                     bf16* __restrict__ gh,
                                                     bf16* __restrict__ gl)
{
    extern __shared__ __align__(16) char sm[];
    bf16*  sXh = (bf16*)(sm + FG_SXH);
    bf16*  sXl = (bf16*)(sm + FG_SXL);
    bf16*  sHh = (bf16*)(sm + FG_SHH);
    bf16*  sHl = (bf16*)(sm + FG_SHL);
    float* sb  = (float*)(sm + FG_SB);

    const int bx = blockIdx.x;
    const int n  = bx & (Ne - 1);
    const int b  = bx >> 4;
    const int t = threadIdx.x;
    const int w = t >> 5, lane = t & 31;
    const int gid = lane >> 2, qid = lane & 3;
    const long long mstep = (long long)NHt;

    for (int h = t; h < HhP; h += 256)
        sb[h] = (h < Hh) ? b1[n * Hh + h] : 0.f;

    #pragma unroll 1
    for (int mm = 0; mm < Mt; ++mm) {
        const long long rb = ((long long)(b * Mt + mm) * Ne + n) * Hh;
        for (int h = t; h < HhP; h += 256) {
            const float v = (h < Hh) ? XW1[rb + h] : 0.f;
            bf16 hi, lo; split2(v, hi, lo);
            sXh[h * XH_STR + mm] = hi;
            sXl[h * XH_STR + mm] = lo;
        }
    }
    __syncthreads();

    float acc[11][4];
    #pragma unroll
    for (int i = 0; i < 11; ++i)
        #pragma unroll
        for (int e = 0; e < 4; ++e) acc[i][e] = 0.f;

    const int NCH = 43;
    const long long dwbn = (long long)(b * Ne + n) * HhP * Mt;
    const int moff = qid * 2;
    const long long c0r = ((long long)(b * Mt + gid) * Ne + n) * Hh;
    const long long c8r = c0r + 8 * mstep;

    uint32_t dah[4], dal[4], cah[4], cal[4];
    {
        const long long r0 = dwbn + (long long)gid * Mt + moff;
        const long long r8 = r0 + 8 * Mt;
        dah[0] = *(const uint32_t*)(dwh + r0);
        dah[1] = *(const uint32_t*)(dwh + r8);
        dah[2] = *(const uint32_t*)(dwh + r0 + 8);
        dah[3] = *(const uint32_t*)(dwh + r8 + 8);
        dal[0] = *(const uint32_t*)(dwl + r0);
        dal[1] = *(const uint32_t*)(dwl + r8);
        dal[2] = *(const uint32_t*)(dwl + r0 + 8);
        dal[3] = *(const uint32_t*)(dwl + r8 + 8);
        const int k0 = qid * 2, k8 = k0 + 8;
        cah[0] = *(const uint32_t*)(chh + c0r + k0);
        cal[0] = *(const uint32_t*)(chl + c0r + k0);
        cah[1] = *(const uint32_t*)(chh + c8r + k0);
        cal[1] = *(const uint32_t*)(chl + c8r + k0);
        cah[2] = *(const uint32_t*)(chh + c0r + k8);
        cal[2] = *(const uint32_t*)(chl + c0r + k8);
        cah[3] = *(const uint32_t*)(chh + c8r + k8);
        cal[3] = *(const uint32_t*)(chl + c8r + k8);
    }

    for (int c = 0; c < NCH; ++c) {
        uint32_t ndah[4], ndal[4], ncah[4], ncal[4];
        if (c + 1 < NCH) {
            const int P0 = (c + 1) * 16;
            const long long r0 = dwbn + (long long)(P0 + gid) * Mt + moff;
            const long long r8 = r0 + 8 * Mt;
            ndah[0] = *(const uint32_t*)(dwh + r0);
            ndah[1] = *(const uint32_t*)(dwh + r8);
            ndah[2] = *(const uint32_t*)(dwh + r0 + 8);
            ndah[3] = *(const uint32_t*)(dwh + r8 + 8);
            ndal[0] = *(const uint32_t*)(dwl + r0);
            ndal[1] = *(const uint32_t*)(dwl + r8);
            ndal[2] = *(const uint32_t*)(dwl + r0 + 8);
            ndal[3] = *(const uint32_t*)(dwl + r8 + 8);
            const int k0 = P0 + qid * 2, k8 = k0 + 8;
            if (k0 + 1 < Hh) {
                ncah[0] = *(const uint32_t*)(chh + c0r + k0);
                ncal[0] = *(const uint32_t*)(chl + c0r + k0);
                ncah[1] = *(const uint32_t*)(chh + c8r + k0);
                ncal[1] = *(const uint32_t*)(chl + c8r + k0);
            } else { ncah[0] = ncal[0] = ncah[1] = ncal[1] = 0; }
            if (k8 + 1 < Hh) {
                ncah[2] = *(const uint32_t*)(chh + c0r + k8);
                ncal[2] = *(const uint32_t*)(chl + c0r + k8);
                ncah[3] = *(const uint32_t*)(chh + c8r + k8);
                ncal[3] = *(const uint32_t*)(chl + c8r + k8);
            } else { ncah[2] = ncal[2] = ncah[3] = ncal[3] = 0; }
        } else {
            #pragma unroll
            for (int i = 0; i < 4; ++i) { ndah[i] = ndal[i] = ncah[i] = ncal[i] = 0; }
        }

        #pragma unroll
        for (int ti = 0; ti < 11; ++ti) {
            const int tw = w + ti * 8;
            if (tw >= NTILE) break;
            const int hrow = tw * 8 + gid;
            const uint32_t xh0 = *(const uint32_t*)(sXh + hrow * XH_STR + qid * 2);
            const uint32_t xh1 = *(const uint32_t*)(sXh + hrow * XH_STR + qid * 2 + 8);
            const uint32_t xl0 = *(const uint32_t*)(sXl + hrow * XH_STR + qid * 2);
            const uint32_t xl1 = *(const uint32_t*)(sXl + hrow * XH_STR + qid * 2 + 8);
            float cf[4] = {0.f, 0.f, 0.f, 0.f};
            mma_bf16(cf, dah[0], dah[1], dah[2], dah[3], xh0, xh1);
            mma_bf16(cf, dah[0], dah[1], dah[2], dah[3], xl0, xl1);
            mma_bf16(cf, dal[0], dal[1], dal[2], dal[3], xh0, xh1);
            const int ha = tw * 8 + qid * 2, hb = ha + 1;
            const float ba = sb[ha], bb = sb[hb];
            const float v00 = fmaxf(cf[0] + ba, 0.f);
            const float v01 = fmaxf(cf[1] + bb, 0.f);
            const float v10 = fmaxf(cf[2] + ba, 0.f);
            const float v11 = fmaxf(cf[3] + bb, 0.f);
            bf16 hi, lo;
            split2(v00, hi, lo); sHh[ha * XH_STR + gid]     = hi; sHl[ha * XH_STR + gid]     = lo;
            split2(v01, hi, lo); sHh[hb * XH_STR + gid]     = hi; sHl[hb * XH_STR + gid]     = lo;
            split2(v10, hi, lo); sHh[ha * XH_STR + gid + 8] = hi; sHl[ha * XH_STR + gid + 8] = lo;
            split2(v11, hi, lo); sHh[hb * XH_STR + gid + 8] = hi; sHl[hb * XH_STR + gid + 8] = lo;
        }
        __syncwarp();

        #pragma unroll
        for (int ti = 0; ti < 11; ++ti) {
            const int tw = w + ti * 8;
            if (tw >= NTILE) break;
            const int hrow = tw * 8 + gid;
            const uint32_t hh0 = *(const uint32_t*)(sHh + hrow * XH_STR + qid * 2);
            const uint32_t hh1 = *(const uint32_t*)(sHh + hrow * XH_STR + qid * 2 + 8);
            const uint32_t hl0 = *(const uint32_t*)(sHl + hrow * XH_STR + qid * 2);
            const uint32_t hl1 = *(const uint32_t*)(sHl + hrow * XH_STR + qid * 2 + 8);
            mma_bf16(acc[ti], cah[0], cah[1], cah[2], cah[3], hh0, hh1);
            mma_bf16(acc[ti], cah[0], cah[1], cah[2], cah[3], hl0, hl1);
            mma_bf16(acc[ti], cal[0], cal[1], cal[2], cal[3], hh0, hh1);
        }
        __syncwarp();

        #pragma unroll
        for (int i = 0; i < 4; ++i) {
            dah[i] = ndah[i]; dal[i] = ndal[i];
            cah[i] = ncah[i]; cal[i] = ncal[i];
        }
    }

    const long long g0 = ((long long)(b * Mt + gid) * Ne + n) * Hh;
    const long long g8 = g0 + 8 * mstep;
    #pragma unroll
    for (int ti = 0; ti < 11; ++ti) {
        const int tw = w + ti * 8;
        if (tw >= NTILE) break;
        const int ha = tw * 8 + qid * 2, hb = ha + 1;
        if (ha < Hh) {
            st_split(gh, gl, g0 + ha, acc[ti][0]);
            st_split(gh, gl, g8 + ha, acc[ti][2]);
        }
        if (hb < Hh) {
            st_split(gh, gl, g0 + hb, acc[ti][1]);
            st_split(gh, gl, g8 + hb, acc[ti][3]);
        }
    }
}

// ---------------- ypart_reduce ----------------
__global__ void ypart_reduce(const float* __restrict__ part, const float* __restrict__ b2s,
                             float* __restrict__ Y)
{
    const int i4 = blockIdx.x * blockDim.x + threadIdx.x;
    const int idx = i4 * 4;
    const int col = idx & (OUTD - 1);
    float4 s = *(const float4*)(b2s + col);
    #pragma unroll
    for (int z = 0; z < YSPLIT; ++z) {
        float4 p = *(const float4*)(part + z * (Rows * OUTD) + idx);
        s.x += p.x; s.y += p.y; s.z += p.z; s.w += p.w;
    }
    *(float4*)(Y + idx) = s;
}

// ---------------- output GEMM ----------------
__global__ __launch_bounds__(128) void out_partial(const float* __restrict__ Y,
                                                   const float* __restrict__ Wout,
                                                   float* __restrict__ part)
{
    constexpr int KC = (Mt * Dd) / OSPLIT;
    __shared__ float ys[Bb][KC];
    const int tid = threadIdx.x;
    const int col = tid * 4;
    const int k0  = blockIdx.y * KC;

    for (int idx = tid; idx < Bb * KC; idx += 128) {
        const int bi = idx / KC, kk = idx - bi * KC;
        ys[bi][kk] = Y[bi * (Mt * Dd) + k0 + kk];
    }
    __syncthreads();

    float4 acc[Bb];
    #pragma unroll
    for (int bi = 0; bi < Bb; ++bi) acc[bi] = make_float4(0.f,0.f,0.f,0.f);

    for (int kk = 0; kk < KC; ++kk) {
        const float4 w = *(const float4*)(Wout + (k0 + kk) * OUTD + col);
        #pragma unroll
        for (int bi = 0; bi < Bb; ++bi) {
            const float yv = ys[bi][kk];
            acc[bi].x = fmaf(yv, w.x, acc[bi].x);
            acc[bi].y = fmaf(yv, w.y, acc[bi].y);
            acc[bi].z = fmaf(yv, w.z, acc[bi].z);
            acc[bi].w = fmaf(yv, w.w, acc[bi].w);
        }
    }
    #pragma unroll
    for (int bi = 0; bi < Bb; ++bi)
        *(float4*)(part + (blockIdx.y * Bb + bi) * OUTD + col) = acc[bi];
}

__global__ void out_reduce(const float* __restrict__ part, const float* __restrict__ bout,
                           float* __restrict__ out)
{
    const int i4 = blockIdx.x * blockDim.x + threadIdx.x;
    const int idx = i4 * 4;
    const int col = idx & (OUTD - 1);
    const int bi  = idx >> 9;
    float4 s = *(const float4*)(bout + col);
    #pragma unroll
    for (int z = 0; z < OSPLIT; ++z) {
        float4 p = *(const float4*)(part + (z * Bb + bi) * OUTD + col);
        s.x += p.x; s.y += p.y; s.z += p.z; s.w += p.w;
    }
    *(float4*)(out + idx) = s;
}

// ---------------- launch ----------------
extern "C" void kernel_launch(void* const* d_in, const int* in_sizes, int n_in,
                              void* d_out, int out_size)
{
    const float* x    = (const float*)d_in[0];
    const float* phi  = (const float*)d_in[1];
    const float* W1   = (const float*)d_in[2];
    const float* b1   = (const float*)d_in[3];
    const float* W2   = (const float*)d_in[4];
    const float* b2   = (const float*)d_in[5];
    const float* Wout = (const float*)d_in[6];
    const float* bout = (const float*)d_in[7];
    float* out = (float*)d_out;

    float *p_logits, *p_XW1, *p_Ypart, *p_Y, *p_b2sum, *p_opart;
    bf16 *p_xh, *p_xl, *p_gh, *p_gl, *p_chh, *p_chl, *p_dwh, *p_dwl;
    cudaGetSymbolAddress((void**)&p_logits, g_logits);
    cudaGetSymbolAddress((void**)&p_XW1,    g_XW1);
    cudaGetSymbolAddress((void**)&p_Ypart,  g_Ypart);
    cudaGetSymbolAddress((void**)&p_Y,      g_Y);
    cudaGetSymbolAddress((void**)&p_b2sum,  g_b2sum);
    cudaGetSymbolAddress((void**)&p_opart,  g_opart);
    cudaGetSymbolAddress((void**)&p_xh,   g_xh);
    cudaGetSymbolAddress((void**)&p_xl,   g_xl);
    cudaGetSymbolAddress((void**)&p_gh,   g_gh);
    cudaGetSymbolAddress((void**)&p_gl,   g_gl);
    cudaGetSymbolAddress((void**)&p_chh,  g_chh);
    cudaGetSymbolAddress((void**)&p_chl,  g_chl);
    cudaGetSymbolAddress((void**)&p_dwh,  g_dwh);
    cudaGetSymbolAddress((void**)&p_dwl,  g_dwl);

    cudaFuncSetAttribute(mma_gemm<0>, cudaFuncAttributeMaxDynamicSharedMemorySize, MG_SMEM);
    cudaFuncSetAttribute(mma_gemm<1>, cudaFuncAttributeMaxDynamicSharedMemorySize, MG_SMEM);
    cudaFuncSetAttribute(fused_G_tc,  cudaFuncAttributeMaxDynamicSharedMemorySize, FG_SMEM);

    const dim3 gBig((NHt + 63)/64, Rows/128, 1);             // 171 x 2

    prep_k<<<CVT_BLOCKS + 2, 256>>>(x, p_xh, p_xl, b2, p_b2sum);                 // 1
    mma_gemm<0><<<gBig, 256, MG_SMEM>>>(p_xh, p_xl, phi, p_logits, NHt, Dd, 1);  // 2
    softdw<<<Rows + (Bb*Ne*HhP)/256, 256>>>(p_logits, p_chh, p_chl, p_dwh, p_dwl); // 3
    mma_gemm<1><<<gBig, 256, MG_SMEM>>>(p_xh, p_xl, W1, p_XW1, NHt, Dd, 1);      // 4 (profiled)

    fused_G_tc<<<Bb*Ne, 256, FG_SMEM>>>(p_XW1, p_dwh, p_dwl, p_chh, p_chl, b1, p_gh, p_gl); // 5

    const dim3 gY(OUTD/64, Rows/128, YSPLIT);                // 8 x 2 x 16
    mma_gemm<0><<<gY, 256, MG_SMEM>>>(p_gh, p_gl, W2, p_Ypart, OUTD, NHt, YSPLIT); // 6
    ypart_reduce<<<(Rows*OUTD/4)/256, 256>>>(p_Ypart, p_b2sum, p_Y);             // 7

    const dim3 gO(1, OSPLIT, 1);
    out_partial<<<gO, 128>>>(p_Y, Wout, p_opart);                                 // 8
    out_reduce <<<(Bb*OUTD/4)/256, 256>>>(p_opart, bout, out);                    // 9
}